// round 6
// baseline (speedup 1.0000x reference)
#include <cuda_runtime.h>
#include <math.h>
#include <stdint.h>

#define BSZ 256
#define TT_ 512
#define ADIM 8
#define ZDIM 4
#define KMIX 3
#define HL 50
#define HID 128
#define NROWS (BSZ*TT_)

// ---------------- scratch (static __device__; cudaMalloc forbidden) ----------------
__device__ float g_buf1[NROWS*HID];
__device__ float g_buf2[NROWS*HID];
__device__ float g_a[NROWS*ADIM];
__device__ float g_alpha[NROWS*KMIX];
__device__ float g_mup[NROWS*ZDIM];
__device__ float g_muf[NROWS*ZDIM];
__device__ float g_J[NROWS*ZDIM*ZDIM];
__device__ float g_mus[NROWS*ZDIM];
__device__ float g_ahat[NROWS*ADIM];

// ---------------- fast activations ----------------
__device__ __forceinline__ float fsig(float x){
    return __fdividef(1.f, 1.f + __expf(-x));
}
__device__ __forceinline__ float ftanh(float x){
    float xc = fminf(fmaxf(x, -15.f), 15.f);
    float t = __expf(2.f*xc);
    return __fdividef(t-1.f, t+1.f);
}

template<int ACT>
__device__ __forceinline__ float actf(float v){
    if (ACT == 1) return ftanh(v);
    if (ACT == 2) return fsig(v);
    return v;
}

// ---------------- tf32 helpers ------------------------------------------------------
__device__ __forceinline__ uint32_t tf32_of(float x){
    uint32_t r;
    asm("cvt.rna.tf32.f32 %0, %1;" : "=r"(r) : "f"(x));
    return r;
}
__device__ __forceinline__ void mma_tf32(float* d, const uint32_t* a, const uint32_t* b){
    asm volatile("mma.sync.aligned.m16n8k8.row.col.f32.tf32.tf32.f32 "
        "{%0,%1,%2,%3},{%4,%5,%6,%7},{%8,%9},{%0,%1,%2,%3};"
        : "+f"(d[0]),"+f"(d[1]),"+f"(d[2]),"+f"(d[3])
        : "r"(a[0]),"r"(a[1]),"r"(a[2]),"r"(a[3]),"r"(b[0]),"r"(b[1]));
}

// ---------------- tf32 tensor-core GEMM: C[M,128] = act(A[M,K] @ W[128,K]^T + b) ----
template<int ACT, bool CONCAT>
__global__ __launch_bounds__(256)
void tgemm128(const float* __restrict__ A0, const float* __restrict__ A1,
              const float* __restrict__ W, const float* __restrict__ bias,
              float* __restrict__ C, int K)
{
    __shared__ __align__(16) float sA[128][36];
    __shared__ __align__(16) float sW[128][36];
    const int tid = threadIdx.x;
    const int wid = tid>>5, ln = tid&31;
    const int g = ln>>2, q = ln&3;
    const int wm = (wid&3)*32;
    const int wn = (wid>>2)*64;
    const int row0 = blockIdx.x*128;

    float d[2][8][4];
#pragma unroll
    for (int mt=0;mt<2;mt++)
#pragma unroll
        for (int nt=0;nt<8;nt++)
#pragma unroll
            for (int i=0;i<4;i++) d[mt][nt][i]=0.f;

    for (int k0=0;k0<K;k0+=32){
        __syncthreads();
#pragma unroll
        for (int it=0;it<4;it++){
            int idx = tid + it*256;
            int r = idx>>3, c4 = (idx&7)*4;
            const float* src;
            if (CONCAT){
                int gk = k0 + c4;
                src = (gk<128)? (A0+(size_t)(row0+r)*128+gk)
                              : (A1+(size_t)(row0+r)*128+(gk-128));
            } else {
                src = A0+(size_t)(row0+r)*K + k0 + c4;
            }
            float4 v = *(const float4*)src;
            float4 o;
            o.x=__uint_as_float(tf32_of(v.x)); o.y=__uint_as_float(tf32_of(v.y));
            o.z=__uint_as_float(tf32_of(v.z)); o.w=__uint_as_float(tf32_of(v.w));
            *(float4*)&sA[r][c4] = o;
        }
#pragma unroll
        for (int it=0;it<4;it++){
            int idx = tid + it*256;
            int n = idx>>3, c4 = (idx&7)*4;
            float4 v = *(const float4*)(W+(size_t)n*K + k0 + c4);
            float4 o;
            o.x=__uint_as_float(tf32_of(v.x)); o.y=__uint_as_float(tf32_of(v.y));
            o.z=__uint_as_float(tf32_of(v.z)); o.w=__uint_as_float(tf32_of(v.w));
            *(float4*)&sW[n][c4] = o;
        }
        __syncthreads();
#pragma unroll
        for (int kk=0;kk<32;kk+=8){
            uint32_t af[2][4];
#pragma unroll
            for (int mt=0;mt<2;mt++){
                int mr = wm + mt*16;
                af[mt][0]=__float_as_uint(sA[mr+g  ][kk+q  ]);
                af[mt][1]=__float_as_uint(sA[mr+g+8][kk+q  ]);
                af[mt][2]=__float_as_uint(sA[mr+g  ][kk+q+4]);
                af[mt][3]=__float_as_uint(sA[mr+g+8][kk+q+4]);
            }
            uint32_t bf[8][2];
#pragma unroll
            for (int nt=0;nt<8;nt++){
                int nc = wn + nt*8 + g;
                bf[nt][0]=__float_as_uint(sW[nc][kk+q  ]);
                bf[nt][1]=__float_as_uint(sW[nc][kk+q+4]);
            }
#pragma unroll
            for (int mt=0;mt<2;mt++)
#pragma unroll
                for (int nt=0;nt<8;nt++)
                    mma_tf32(d[mt][nt], af[mt], bf[nt]);
        }
    }
#pragma unroll
    for (int mt=0;mt<2;mt++){
        int r_top = row0 + wm + mt*16 + g;
#pragma unroll
        for (int nt=0;nt<8;nt++){
            int col = wn + nt*8 + 2*q;
            float b0v = bias[col], b1v = bias[col+1];
            float2 o0, o1;
            o0.x = actf<ACT>(d[mt][nt][0]+b0v);
            o0.y = actf<ACT>(d[mt][nt][1]+b1v);
            o1.x = actf<ACT>(d[mt][nt][2]+b0v);
            o1.y = actf<ACT>(d[mt][nt][3]+b1v);
            *(float2*)&C[(size_t)r_top*128 + col]     = o0;
            *(float2*)&C[(size_t)(r_top+8)*128 + col] = o1;
        }
    }
}

// ---------------- encoder layer 3: a = Y2 @ Wm^T + bm + eps  (N=8, K=128) ----------
__global__ __launch_bounds__(256)
void enc3_kernel(const float* __restrict__ Y2, const float* __restrict__ Wm,
                 const float* __restrict__ bm, const float* __restrict__ eps,
                 float* __restrict__ aout)
{
    __shared__ __align__(16) float sW[8][128];
    for (int i=threadIdx.x;i<1024;i+=256) sW[i>>7][i&127]=Wm[i];
    __syncthreads();
    int r = blockIdx.x*32 + (threadIdx.x>>3);
    int n = threadIdx.x&7;
    const float4* y = (const float4*)(Y2 + (size_t)r*128);
    const float4* w = (const float4*)&sW[n][0];
    float s=0.f;
#pragma unroll
    for (int k=0;k<32;k++){
        float4 yv=y[k], wv=w[k];
        s += yv.x*wv.x+yv.y*wv.y+yv.z*wv.z+yv.w*wv.w;
    }
    aout[(size_t)r*8+n] = s + bm[n] + eps[(size_t)r*8+n];
}

// ---------------- LSTM + alpha: TWO batches per block (grid 128 <= 148 SMs) --------
// Each 256-thread half handles one batch exactly like the R3 kernel; one
// __syncthreads serves both halves.
__global__ __launch_bounds__(512)
void lstm_kernel(const float* __restrict__ a, const float* __restrict__ a_init,
                 const float* __restrict__ Wih, const float* __restrict__ Whh,
                 const float* __restrict__ bih, const float* __restrict__ bhh,
                 const float* __restrict__ aW, const float* __restrict__ ab,
                 float* __restrict__ alpha)
{
    __shared__ __align__(16) float4 shv[2][13];     // h per sub-batch (52 padded)
    __shared__ __align__(16) float4 sxv[2][2][2];   // [sub][buf] x_t (8)
    __shared__ float spre[2][200];
    __shared__ __align__(16) float4 saWv[3][13];
    __shared__ float sab_s[3];
    __shared__ float slog[2][3];
    int tid=threadIdx.x;
    int sub=tid>>8, stid=tid&255;
    int b=blockIdx.x*2+sub;

    float wih[8], whh[52], bsum=0.f, c=0.f;
    if (stid<200){
#pragma unroll
        for (int j=0;j<8;j++) wih[j]=Wih[stid*8+j];
#pragma unroll
        for (int j=0;j<50;j++) whh[j]=Whh[stid*50+j];
        whh[50]=0.f; whh[51]=0.f;
        bsum = bih[stid]+bhh[stid];
    }
    for (int i=tid;i<3*52;i+=512){
        int row=i/52, col=i%52;
        ((float*)saWv)[i] = (col<50)? aW[row*50+col] : 0.f;
    }
    if (tid<3) sab_s[tid]=ab[tid];
    for (int i=tid;i<104;i+=512) ((float*)shv)[i]=0.f;
    if (tid<16){                                  // sxv[sub][0] = a_init
        int s2=tid>>3, k=tid&7;
        ((float*)sxv)[s2*16 + k]=a_init[k];
    }
    __syncthreads();

    for (int t=0;t<TT_;t++){
        int pb = t&1;
        // ---- P1 ----
        if (stid<200){
            const float4* xv = sxv[sub][pb];
            float4 x0=xv[0], x1=xv[1];
            float a0 = bsum + wih[0]*x0.x + wih[4]*x1.x;
            float a1 = wih[1]*x0.y + wih[5]*x1.y;
            float a2 = wih[2]*x0.z + wih[6]*x1.z;
            float a3 = wih[3]*x0.w + wih[7]*x1.w;
#pragma unroll
            for (int q=0;q<13;q++){
                float4 hv=shv[sub][q];
                a0 += whh[4*q+0]*hv.x;
                a1 += whh[4*q+1]*hv.y;
                a2 += whh[4*q+2]*hv.z;
                a3 += whh[4*q+3]*hv.w;
            }
            spre[sub][stid]=(a0+a1)+(a2+a3);
        } else if (stid>=224 && stid<227){
            if (t>0){
                int k=stid-224;
                float a0=0,a1=0,a2=0,a3=0;
#pragma unroll
                for (int q=0;q<13;q++){
                    float4 wv=saWv[k][q], hv=shv[sub][q];
                    a0+=wv.x*hv.x; a1+=wv.y*hv.y; a2+=wv.z*hv.z; a3+=wv.w*hv.w;
                }
                slog[sub][k]=(a0+a1)+(a2+a3)+sab_s[k];
            }
        } else if (stid>=232 && stid<240){
            if (t<TT_-1)
                ((float*)sxv[sub][pb^1])[stid-232] = a[((size_t)b*TT_+t)*8 + (stid-232)];
        }
        __syncthreads();
        // ---- P2 ----
        if (stid<50){
            float pi=spre[sub][stid], pf=spre[sub][50+stid];
            float pg=spre[sub][100+stid], po=spre[sub][150+stid];
            float ig=fsig(pi);
            float fg=fsig(pf);
            float gg=ftanh(pg);
            float og=fsig(po);
            c = fg*c + ig*gg;
            ((float*)shv[sub])[stid] = og*ftanh(c);
        } else if (stid>=224 && stid<227 && t>0){
            int k=stid-224;
            float l0=slog[sub][0],l1=slog[sub][1],l2=slog[sub][2];
            float mx=fmaxf(l0,fmaxf(l1,l2));
            float e0=__expf(l0-mx),e1=__expf(l1-mx),e2=__expf(l2-mx);
            float inv=__fdividef(1.f, e0+e1+e2);
            float mine=(k==0)?e0:((k==1)?e1:e2);
            alpha[((size_t)b*TT_+t-1)*3+k]=mine*inv;
        }
        __syncthreads();
    }
    // final alpha (t = T-1) from latest h
    if (stid>=224 && stid<227){
        int k=stid-224;
        float lg[3];
#pragma unroll
        for (int kk=0;kk<3;kk++){
            float a0=0,a1=0,a2=0,a3=0;
#pragma unroll
            for (int q=0;q<13;q++){
                float4 wv=saWv[kk][q], hv=shv[sub][q];
                a0+=wv.x*hv.x; a1+=wv.y*hv.y; a2+=wv.z*hv.z; a3+=wv.w*hv.w;
            }
            lg[kk]=(a0+a1)+(a2+a3)+sab_s[kk];
        }
        float mx=fmaxf(lg[0],fmaxf(lg[1],lg[2]));
        float e0=__expf(lg[0]-mx),e1=__expf(lg[1]-mx),e2=__expf(lg[2]-mx);
        float inv=__fdividef(1.f, e0+e1+e2);
        float mine=(k==0)?e0:((k==1)?e1:e2);
        alpha[((size_t)b*TT_+TT_-1)*3+k]=mine*inv;
    }
}

// ---------------- 4x4 determinant + adjugate helpers --------------------------------
__device__ __forceinline__ float det4s(const float* m){
    float m00=m[0],m01=m[1],m02=m[2],m03=m[3];
    float m10=m[4],m11=m[5],m12=m[6],m13=m[7];
    float m20=m[8],m21=m[9],m22=m[10],m23=m[11];
    float m30=m[12],m31=m[13],m32=m[14],m33=m[15];
    return m00*(m11*(m22*m33-m23*m32)-m12*(m21*m33-m23*m31)+m13*(m21*m32-m22*m31))
         - m01*(m10*(m22*m33-m23*m32)-m12*(m20*m33-m23*m30)+m13*(m20*m32-m22*m30))
         + m02*(m10*(m21*m33-m23*m31)-m11*(m20*m33-m23*m30)+m13*(m20*m31-m21*m30))
         - m03*(m10*(m21*m32-m22*m31)-m11*(m20*m32-m22*m30)+m12*(m20*m31-m21*m30));
}

__device__ __forceinline__ float adj_entry(const float* m, int l){
    int r=l>>2, c=l&3;
    int rr[3], cc[3];
    int p=0;
#pragma unroll
    for (int k=0;k<4;k++) if (k!=c) rr[p++]=k;
    p=0;
#pragma unroll
    for (int k=0;k<4;k++) if (k!=r) cc[p++]=k;
    float a00=m[rr[0]*4+cc[0]], a01=m[rr[0]*4+cc[1]], a02=m[rr[0]*4+cc[2]];
    float a10=m[rr[1]*4+cc[0]], a11=m[rr[1]*4+cc[1]], a12=m[rr[1]*4+cc[2]];
    float a20=m[rr[2]*4+cc[0]], a21=m[rr[2]*4+cc[1]], a22=m[rr[2]*4+cc[2]];
    float d = a00*(a11*a22-a12*a21) - a01*(a10*a22-a12*a20) + a02*(a10*a21-a11*a20);
    return ((r+c)&1)? -d : d;
}

// ---------------- Kalman forward + smoother gains (information form, 8 phases) -----
#define KO_AM   0
#define KO_BM   16
#define KO_CM   52
#define KO_SIG  84
#define KO_SIGP 100
#define KO_PADJ 116
#define KO_CTC  132
#define KO_N    148
#define KO_NADJ 164
#define KO_T2   180
#define KO_JT   196
#define KO_W    212
#define KO_MU   244
#define KO_MUP  248
#define KO_RES  252
#define KO_AT   260
#define KO_UT   268
#define KO_AL   277
#define KO_SC   280
#define KWSZ    288

__global__ __launch_bounds__(64)
void kf_forward(const float* __restrict__ alpha, const float* __restrict__ a,
                const float* __restrict__ a_init, const float* __restrict__ u_ext,
                const float* __restrict__ Ag, const float* __restrict__ Bg,
                const float* __restrict__ Cg,
                float* __restrict__ mu_p_g, float* __restrict__ mu_f_g,
                float* __restrict__ Jg)
{
    __shared__ float sA[48], sB[108], sC[96];
    __shared__ float wsm[2][KWSZ];
    const float qn=0.08f, ir=1.f/0.03f;
    int w = threadIdx.x>>5, ln = threadIdx.x&31;
    int b = blockIdx.x*2 + w;
    for (int i=threadIdx.x;i<48;i+=64) sA[i]=Ag[i];
    for (int i=threadIdx.x;i<108;i+=64) sB[i]=Bg[i];
    for (int i=threadIdx.x;i<96;i+=64) sC[i]=Cg[i];
    __syncthreads();
    float* s = wsm[w];

    float r_al=0.f, r_a=0.f, r_u=0.f, r_ap=0.f;
    if (ln<3)            r_al = alpha[(size_t)b*TT_*3 + ln];
    if (ln>=4 && ln<12){ r_a  = a[(size_t)b*TT_*8 + (ln-4)]; r_ap = a_init[ln-4]; }
    if (ln==12)          r_u  = u_ext[(size_t)b*TT_];

    for (int t=0;t<TT_;t++){
        size_t bt = (size_t)b*TT_ + t;
        // ---- P0: publish step inputs ----
        if (ln<3) s[KO_AL+ln]=r_al;
        if (ln>=4 && ln<12){ s[KO_AT+ln-4]=r_a; s[KO_UT+ln-4]=r_ap; r_ap=r_a; }
        if (ln==12) s[KO_UT+8]=r_u;
        __syncwarp();
        if (t+1<TT_){
            if (ln<3)            r_al = alpha[(bt+1)*3+ln];
            if (ln>=4 && ln<12)  r_a  = a[(bt+1)*8 + (ln-4)];
            if (ln==12)          r_u  = u_ext[bt+1];
        }
        // ---- P1: mix Am/Bm/Cm ----
        float al0=s[KO_AL], al1=s[KO_AL+1], al2=s[KO_AL+2];
        for (int f=ln; f<84; f+=32){
            if (f<16)      s[KO_AM+f] = al0*sA[f] + al1*sA[16+f] + al2*sA[32+f];
            else if (f<52){int j2=f-16; s[KO_BM+j2]=al0*sB[j2]+al1*sB[36+j2]+al2*sB[72+j2];}
            else          {int j2=f-52; s[KO_CM+j2]=al0*sC[j2]+al1*sC[32+j2]+al2*sC[64+j2];}
        }
        __syncwarp();
        // ---- P2: mu_p ; Sig_p ; CtC/r ----
        if (t==0){
            if (ln<4) s[KO_MUP+ln]=0.f;
            if (ln>=16){int l=ln-16; s[KO_SIGP+l]=((l>>2)==(l&3))?20.f:0.f;}
        } else {
            if (ln<4){
                float v=0.f;
#pragma unroll
                for (int j=0;j<4;j++) v += s[KO_AM+ln*4+j]*s[KO_MU+j];
#pragma unroll
                for (int j=0;j<9;j++) v += s[KO_BM+ln*9+j]*s[KO_UT+j];
                s[KO_MUP+ln]=v;
            }
            if (ln>=16){
                int l=ln-16, i=l>>2, j=l&3;
                float v=(i==j)?qn:0.f;
#pragma unroll
                for (int k=0;k<4;k++){
                    float inner=0.f;
#pragma unroll
                    for (int q=0;q<4;q++) inner += s[KO_SIG+k*4+q]*s[KO_AM+j*4+q];
                    v += s[KO_AM+i*4+k]*inner;
                }
                s[KO_SIGP+l]=v;
            }
        }
        if (ln>=4 && ln<14){
            const int pi_[10]={0,0,0,0,1,1,1,2,2,3};
            const int pj_[10]={0,1,2,3,1,2,3,2,3,3};
            int l=ln-4, i=pi_[l], j=pj_[l];
            float v=0.f;
#pragma unroll
            for (int cc=0;cc<8;cc++) v += s[KO_CM+cc*4+i]*s[KO_CM+cc*4+j];
            v*=ir;
            s[KO_CTC+i*4+j]=v; s[KO_CTC+j*4+i]=v;
        }
        __syncwarp();
        // ---- P3: PADJ ; T2 = Sig_f_prev * Am^T ----
        if (ln<16) s[KO_PADJ+ln]=adj_entry(s+KO_SIGP, ln);
        else if (t>0){
            int l=ln-16, i=l>>2, j=l&3; float v=0.f;
#pragma unroll
            for (int k=0;k<4;k++) v += s[KO_SIG+i*4+k]*s[KO_AM+j*4+k];
            s[KO_T2+l]=v;
        }
        __syncwarp();
        // ---- P4: detP ; res = a - C mu_p ; JT = T2 * PADJ ----
        if (ln==0){
            float dp = s[KO_SIGP+0]*s[KO_PADJ+0] + s[KO_SIGP+1]*s[KO_PADJ+4]
                     + s[KO_SIGP+2]*s[KO_PADJ+8] + s[KO_SIGP+3]*s[KO_PADJ+12];
            s[KO_SC+0]=dp;
            s[KO_SC+1]=__fdividef(1.f,dp);
        }
        if (ln>=8 && ln<16){
            int cc=ln-8; float v=s[KO_AT+cc];
#pragma unroll
            for (int k=0;k<4;k++) v -= s[KO_CM+cc*4+k]*s[KO_MUP+k];
            s[KO_RES+cc]=v;
        }
        if (t>0 && ln>=16){
            int l=ln-16, i=l>>2, j=l&3; float v=0.f;
#pragma unroll
            for (int k=0;k<4;k++) v += s[KO_T2+i*4+k]*s[KO_PADJ+k*4+j];
            s[KO_JT+l]=v;
        }
        __syncwarp();
        // ---- P5: N = PADJ + detP*CtC/r ; J_{t-1} -> global ----
        if (ln<16) s[KO_N+ln] = s[KO_PADJ+ln] + s[KO_SC+0]*s[KO_CTC+ln];
        else if (t>0){
            int l=ln-16;
            Jg[(bt-1)*16 + l] = s[KO_JT+l]*s[KO_SC+1];
        }
        __syncwarp();
        // ---- P6: NADJ ; w = C^T res ; detN + scales ----
        if (ln<16) s[KO_NADJ+ln]=adj_entry(s+KO_N, ln);
        else if (ln<20){
            int i=ln-16; float v=0.f;
#pragma unroll
            for (int cc=0;cc<8;cc++) v += s[KO_CM+cc*4+i]*s[KO_RES+cc];
            s[KO_W+i]=v;
        } else if (ln==20){
            float dn = det4s(s+KO_N);
            float sc = __fdividef(s[KO_SC+0], dn);   // Sig_f = NADJ * sc
            s[KO_SC+2]=sc;
            s[KO_SC+3]=sc*ir;                        // mu gain scale
        }
        __syncwarp();
        // ---- P7: Sig_f ; mu_f = mu_p + sc*ir*NADJ*w ; stores ----
        if (ln>=16){
            int l=ln-16;
            s[KO_SIG+l]=s[KO_NADJ+l]*s[KO_SC+2];
        }
        if (ln<4){
            float acc=0.f;
#pragma unroll
            for (int k=0;k<4;k++) acc += s[KO_NADJ+ln*4+k]*s[KO_W+k];
            float v = s[KO_MUP+ln] + acc*s[KO_SC+3];
            s[KO_MU+ln]=v;
            mu_f_g[bt*4+ln]=v;
        }
        if (ln>=4 && ln<8) mu_p_g[bt*4+ln-4]=s[KO_MUP+ln-4];
        __syncwarp();
    }
}

// ---------------- backward mu_smooth recursion (4 lanes per batch, prefetched) ------
__global__ __launch_bounds__(32)
void smooth_kernel(const float* __restrict__ mu_f, const float* __restrict__ mu_p,
                   const float* __restrict__ Jg, float* __restrict__ mus)
{
    int tid = threadIdx.x;
    int g = blockIdx.x*8 + (tid>>2);
    int i = tid & 3;
    size_t base = (size_t)g*TT_;
    float v = mu_f[(base+TT_-1)*4 + i];
    mus[(base+TT_-1)*4 + i] = v;
    unsigned gb = tid & ~3u;
    float4 Jr = *(const float4*)&Jg[(base+TT_-2)*16 + i*4];
    float mf = mu_f[(base+TT_-2)*4 + i];
    float mp = mu_p[(base+TT_-1)*4 + i];
    for (int t=TT_-2; t>=0; t--){
        float4 Jn; float mfn=0.f, mpn=0.f;
        if (t>0){
            Jn  = *(const float4*)&Jg[(base+t-1)*16 + i*4];
            mfn = mu_f[(base+t-1)*4 + i];
            mpn = mu_p[(base+t)*4 + i];
        } else { Jn = Jr; }
        float mi = v - mp;
        float m0=__shfl_sync(0xffffffffu, mi, gb+0);
        float m1=__shfl_sync(0xffffffffu, mi, gb+1);
        float m2=__shfl_sync(0xffffffffu, mi, gb+2);
        float m3=__shfl_sync(0xffffffffu, mi, gb+3);
        v = mf + Jr.x*m0 + Jr.y*m1 + Jr.z*m2 + Jr.w*m3;
        mus[(base+t)*4+i]=v;
        Jr=Jn; mf=mfn; mp=mpn;
    }
}

// ---------------- a_hat = C_mix mu_smooth -------------------------------------------
__global__ void ahat_kernel(const float* __restrict__ alpha, const float* __restrict__ mus,
                            const float* __restrict__ Cg, float* __restrict__ ahat)
{
    int idx = blockIdx.x*blockDim.x + threadIdx.x;
    if (idx >= NROWS) return;
    float a0=alpha[(size_t)idx*3+0], a1=alpha[(size_t)idx*3+1], a2=alpha[(size_t)idx*3+2];
    float4 mu = *(const float4*)&mus[(size_t)idx*4];
    float mv[4]={mu.x,mu.y,mu.z,mu.w};
#pragma unroll
    for (int r=0;r<8;r++){
        float v=0.f;
#pragma unroll
        for (int j=0;j<4;j++){
            float cm = a0*__ldg(&Cg[r*4+j]) + a1*__ldg(&Cg[32+r*4+j]) + a2*__ldg(&Cg[64+r*4+j]);
            v += cm*mv[j];
        }
        ahat[(size_t)idx*8+r]=v;
    }
}

// ---------------- decoder layer 1: d1 = tanh(ahat @ W^T + b) (K=8) ------------------
__global__ __launch_bounds__(256)
void dec1_kernel(const float* __restrict__ ahat, const float* __restrict__ W,
                 const float* __restrict__ bvec, float* __restrict__ out)
{
    __shared__ float sa[16][8];
    int tid = threadIdx.x;
    int r0 = blockIdx.x*16;
    if (tid<128) sa[tid>>3][tid&7] = ahat[(size_t)r0*8 + tid];
    int n = tid & 127;
    float w[8];
#pragma unroll
    for (int j=0;j<8;j++) w[j]=W[n*8+j];
    float bb=bvec[n];
    __syncthreads();
    int half = tid>>7;
#pragma unroll
    for (int q=0;q<8;q++){
        int rl = half*8+q;
        float s=bb;
#pragma unroll
        for (int j=0;j<8;j++) s += sa[rl][j]*w[j];
        out[(size_t)(r0+rl)*128 + n] = ftanh(s);
    }
}

// ---------------- launcher ----------------------------------------------------------
extern "C" void kernel_launch(void* const* d_in, const int* in_sizes, int n_in,
                              void* d_out, int out_size)
{
    const float* x       = (const float*)d_in[0];
    const float* m       = (const float*)d_in[1];
    const float* u_ext   = (const float*)d_in[2];
    const float* eps     = (const float*)d_in[3];
    const float* enc_W1  = (const float*)d_in[4];
    const float* enc_b1  = (const float*)d_in[5];
    const float* enc_W2  = (const float*)d_in[6];
    const float* enc_b2  = (const float*)d_in[7];
    const float* W_mean  = (const float*)d_in[8];
    const float* b_mean  = (const float*)d_in[9];
    const float* Amat    = (const float*)d_in[10];
    const float* Bmat    = (const float*)d_in[11];
    const float* Cmat    = (const float*)d_in[12];
    const float* a_init  = (const float*)d_in[13];
    const float* lstm_Wih= (const float*)d_in[14];
    const float* lstm_Whh= (const float*)d_in[15];
    const float* lstm_bih= (const float*)d_in[16];
    const float* lstm_bhh= (const float*)d_in[17];
    const float* alpha_W = (const float*)d_in[18];
    const float* alpha_b = (const float*)d_in[19];
    const float* dec_W1  = (const float*)d_in[20];
    const float* dec_b1  = (const float*)d_in[21];
    const float* dec_W2  = (const float*)d_in[22];
    const float* dec_b2  = (const float*)d_in[23];
    const float* gen_W   = (const float*)d_in[24];
    const float* gen_b   = (const float*)d_in[25];

    float *p_buf1,*p_buf2,*p_a,*p_alpha,*p_mup,*p_muf,*p_J,*p_mus,*p_ahat;
    cudaGetSymbolAddress((void**)&p_buf1,  g_buf1);
    cudaGetSymbolAddress((void**)&p_buf2,  g_buf2);
    cudaGetSymbolAddress((void**)&p_a,     g_a);
    cudaGetSymbolAddress((void**)&p_alpha, g_alpha);
    cudaGetSymbolAddress((void**)&p_mup,   g_mup);
    cudaGetSymbolAddress((void**)&p_muf,   g_muf);
    cudaGetSymbolAddress((void**)&p_J,     g_J);
    cudaGetSymbolAddress((void**)&p_mus,   g_mus);
    cudaGetSymbolAddress((void**)&p_ahat,  g_ahat);

    // encoder (tf32 tensor cores)
    tgemm128<1,true ><<<NROWS/128,256>>>(x, m, enc_W1, enc_b1, p_buf1, 256);
    tgemm128<1,false><<<NROWS/128,256>>>(p_buf1, nullptr, enc_W2, enc_b2, p_buf2, 128);
    enc3_kernel<<<NROWS/32,256>>>(p_buf2, W_mean, b_mean, eps, p_a);
    // LSTM -> alpha  (2 batches per block; grid 128 <= 148 SMs)
    lstm_kernel<<<BSZ/2,512>>>(p_a, a_init, lstm_Wih, lstm_Whh, lstm_bih, lstm_bhh,
                               alpha_W, alpha_b, p_alpha);
    // Kalman forward (+ fused smoother gains J)
    kf_forward<<<BSZ/2,64>>>(p_alpha, p_a, a_init, u_ext, Amat, Bmat, Cmat,
                             p_mup, p_muf, p_J);
    // backward mu recursion
    smooth_kernel<<<32,32>>>(p_muf, p_mup, p_J, p_mus);
    ahat_kernel<<<NROWS/256,256>>>(p_alpha, p_mus, Cmat, p_ahat);
    // decoder (tf32 tensor cores)
    dec1_kernel<<<NROWS/16,256>>>(p_ahat, dec_W1, dec_b1, p_buf1);
    tgemm128<1,false><<<NROWS/128,256>>>(p_buf1, nullptr, dec_W2, dec_b2, p_buf2, 128);
    tgemm128<2,false><<<NROWS/128,256>>>(p_buf2, nullptr, gen_W, gen_b, (float*)d_out, 128);
    (void)in_sizes; (void)n_in; (void)out_size;
}

// round 7
// speedup vs baseline: 1.1318x; 1.1318x over previous
#include <cuda_runtime.h>
#include <math.h>
#include <stdint.h>

#define BSZ 256
#define TT_ 512
#define ADIM 8
#define ZDIM 4
#define KMIX 3
#define HL 50
#define HID 128
#define NROWS (BSZ*TT_)

// ---------------- scratch (static __device__; cudaMalloc forbidden) ----------------
__device__ float g_buf1[NROWS*HID];
__device__ float g_buf2[NROWS*HID];
__device__ float g_a[NROWS*ADIM];
__device__ float g_alpha[NROWS*KMIX];
__device__ float g_mup[NROWS*ZDIM];
__device__ float g_muf[NROWS*ZDIM];
__device__ float g_J[NROWS*ZDIM*ZDIM];
__device__ float g_mus[NROWS*ZDIM];
__device__ float g_ahat[NROWS*ADIM];

// ---------------- fast activations ----------------
__device__ __forceinline__ float fsig(float x){
    return __fdividef(1.f, 1.f + __expf(-x));
}
__device__ __forceinline__ float ftanh(float x){
    float xc = fminf(fmaxf(x, -15.f), 15.f);
    float t = __expf(2.f*xc);
    return __fdividef(t-1.f, t+1.f);
}

template<int ACT>
__device__ __forceinline__ float actf(float v){
    if (ACT == 1) return ftanh(v);
    if (ACT == 2) return fsig(v);
    return v;
}

// ---------------- tf32 helpers ------------------------------------------------------
__device__ __forceinline__ uint32_t tf32_of(float x){
    uint32_t r;
    asm("cvt.rna.tf32.f32 %0, %1;" : "=r"(r) : "f"(x));
    return r;
}
__device__ __forceinline__ void mma_tf32(float* d, const uint32_t* a, const uint32_t* b){
    asm volatile("mma.sync.aligned.m16n8k8.row.col.f32.tf32.tf32.f32 "
        "{%0,%1,%2,%3},{%4,%5,%6,%7},{%8,%9},{%0,%1,%2,%3};"
        : "+f"(d[0]),"+f"(d[1]),"+f"(d[2]),"+f"(d[3])
        : "r"(a[0]),"r"(a[1]),"r"(a[2]),"r"(a[3]),"r"(b[0]),"r"(b[1]));
}

// ---------------- tf32 tensor-core GEMM: C[M,128] = act(A[M,K] @ W[128,K]^T + b) ----
template<int ACT, bool CONCAT>
__global__ __launch_bounds__(256)
void tgemm128(const float* __restrict__ A0, const float* __restrict__ A1,
              const float* __restrict__ W, const float* __restrict__ bias,
              float* __restrict__ C, int K)
{
    __shared__ __align__(16) float sA[128][36];
    __shared__ __align__(16) float sW[128][36];
    const int tid = threadIdx.x;
    const int wid = tid>>5, ln = tid&31;
    const int g = ln>>2, q = ln&3;
    const int wm = (wid&3)*32;
    const int wn = (wid>>2)*64;
    const int row0 = blockIdx.x*128;

    float d[2][8][4];
#pragma unroll
    for (int mt=0;mt<2;mt++)
#pragma unroll
        for (int nt=0;nt<8;nt++)
#pragma unroll
            for (int i=0;i<4;i++) d[mt][nt][i]=0.f;

    for (int k0=0;k0<K;k0+=32){
        __syncthreads();
#pragma unroll
        for (int it=0;it<4;it++){
            int idx = tid + it*256;
            int r = idx>>3, c4 = (idx&7)*4;
            const float* src;
            if (CONCAT){
                int gk = k0 + c4;
                src = (gk<128)? (A0+(size_t)(row0+r)*128+gk)
                              : (A1+(size_t)(row0+r)*128+(gk-128));
            } else {
                src = A0+(size_t)(row0+r)*K + k0 + c4;
            }
            float4 v = *(const float4*)src;
            float4 o;
            o.x=__uint_as_float(tf32_of(v.x)); o.y=__uint_as_float(tf32_of(v.y));
            o.z=__uint_as_float(tf32_of(v.z)); o.w=__uint_as_float(tf32_of(v.w));
            *(float4*)&sA[r][c4] = o;
        }
#pragma unroll
        for (int it=0;it<4;it++){
            int idx = tid + it*256;
            int n = idx>>3, c4 = (idx&7)*4;
            float4 v = *(const float4*)(W+(size_t)n*K + k0 + c4);
            float4 o;
            o.x=__uint_as_float(tf32_of(v.x)); o.y=__uint_as_float(tf32_of(v.y));
            o.z=__uint_as_float(tf32_of(v.z)); o.w=__uint_as_float(tf32_of(v.w));
            *(float4*)&sW[n][c4] = o;
        }
        __syncthreads();
#pragma unroll
        for (int kk=0;kk<32;kk+=8){
            uint32_t af[2][4];
#pragma unroll
            for (int mt=0;mt<2;mt++){
                int mr = wm + mt*16;
                af[mt][0]=__float_as_uint(sA[mr+g  ][kk+q  ]);
                af[mt][1]=__float_as_uint(sA[mr+g+8][kk+q  ]);
                af[mt][2]=__float_as_uint(sA[mr+g  ][kk+q+4]);
                af[mt][3]=__float_as_uint(sA[mr+g+8][kk+q+4]);
            }
            uint32_t bf[8][2];
#pragma unroll
            for (int nt=0;nt<8;nt++){
                int nc = wn + nt*8 + g;
                bf[nt][0]=__float_as_uint(sW[nc][kk+q  ]);
                bf[nt][1]=__float_as_uint(sW[nc][kk+q+4]);
            }
#pragma unroll
            for (int mt=0;mt<2;mt++)
#pragma unroll
                for (int nt=0;nt<8;nt++)
                    mma_tf32(d[mt][nt], af[mt], bf[nt]);
        }
    }
#pragma unroll
    for (int mt=0;mt<2;mt++){
        int r_top = row0 + wm + mt*16 + g;
#pragma unroll
        for (int nt=0;nt<8;nt++){
            int col = wn + nt*8 + 2*q;
            float b0v = bias[col], b1v = bias[col+1];
            float2 o0, o1;
            o0.x = actf<ACT>(d[mt][nt][0]+b0v);
            o0.y = actf<ACT>(d[mt][nt][1]+b1v);
            o1.x = actf<ACT>(d[mt][nt][2]+b0v);
            o1.y = actf<ACT>(d[mt][nt][3]+b1v);
            *(float2*)&C[(size_t)r_top*128 + col]     = o0;
            *(float2*)&C[(size_t)(r_top+8)*128 + col] = o1;
        }
    }
}

// ---------------- encoder layer 3: a = Y2 @ Wm^T + bm + eps  (N=8, K=128) ----------
__global__ __launch_bounds__(256)
void enc3_kernel(const float* __restrict__ Y2, const float* __restrict__ Wm,
                 const float* __restrict__ bm, const float* __restrict__ eps,
                 float* __restrict__ aout)
{
    __shared__ __align__(16) float sW[8][128];
    for (int i=threadIdx.x;i<1024;i+=256) sW[i>>7][i&127]=Wm[i];
    __syncthreads();
    int r = blockIdx.x*32 + (threadIdx.x>>3);
    int n = threadIdx.x&7;
    const float4* y = (const float4*)(Y2 + (size_t)r*128);
    const float4* w = (const float4*)&sW[n][0];
    float s=0.f;
#pragma unroll
    for (int k=0;k<32;k++){
        float4 yv=y[k], wv=w[k];
        s += yv.x*wv.x+yv.y*wv.y+yv.z*wv.z+yv.w*wv.w;
    }
    aout[(size_t)r*8+n] = s + bm[n] + eps[(size_t)r*8+n];
}

// ---------------- LSTM + alpha (R3/R5 version): 2 syncs/step, pipelined alpha ------
__global__ __launch_bounds__(256)
void lstm_kernel(const float* __restrict__ a, const float* __restrict__ a_init,
                 const float* __restrict__ Wih, const float* __restrict__ Whh,
                 const float* __restrict__ bih, const float* __restrict__ bhh,
                 const float* __restrict__ aW, const float* __restrict__ ab,
                 float* __restrict__ alpha)
{
    __shared__ __align__(16) float4 shv[13];      // h, padded to 52
    __shared__ __align__(16) float4 sxv[2][2];    // x_t, double buffered (8)
    __shared__ float spre[200];
    __shared__ __align__(16) float4 saWv[3][13];
    __shared__ float sab_s[3];
    __shared__ float slog[3];
    int tid=threadIdx.x; int b=blockIdx.x;

    float wih[8], whh[52], bsum=0.f, c=0.f;
    if (tid<200){
#pragma unroll
        for (int j=0;j<8;j++) wih[j]=Wih[tid*8+j];
#pragma unroll
        for (int j=0;j<50;j++) whh[j]=Whh[tid*50+j];
        whh[50]=0.f; whh[51]=0.f;
        bsum = bih[tid]+bhh[tid];
    }
    for (int i=tid;i<3*52;i+=256){
        int row=i/52, col=i%52;
        ((float*)saWv)[i] = (col<50)? aW[row*50+col] : 0.f;
    }
    if (tid<3) sab_s[tid]=ab[tid];
    for (int i=tid;i<52;i+=256) ((float*)shv)[i]=0.f;
    if (tid<8) ((float*)sxv)[tid]=a_init[tid];    // sxv[0] = a_init
    __syncthreads();

    for (int t=0;t<TT_;t++){
        int pb = t&1;
        // ---- P1 ----
        if (tid<200){
            const float4* xv = sxv[pb];
            float4 x0=xv[0], x1=xv[1];
            float a0 = bsum + wih[0]*x0.x + wih[4]*x1.x;
            float a1 = wih[1]*x0.y + wih[5]*x1.y;
            float a2 = wih[2]*x0.z + wih[6]*x1.z;
            float a3 = wih[3]*x0.w + wih[7]*x1.w;
#pragma unroll
            for (int q=0;q<13;q++){
                float4 hv=shv[q];
                a0 += whh[4*q+0]*hv.x;
                a1 += whh[4*q+1]*hv.y;
                a2 += whh[4*q+2]*hv.z;
                a3 += whh[4*q+3]*hv.w;
            }
            spre[tid]=(a0+a1)+(a2+a3);
        } else if (tid>=224 && tid<227){
            if (t>0){
                int k=tid-224;
                float a0=0,a1=0,a2=0,a3=0;
#pragma unroll
                for (int q=0;q<13;q++){
                    float4 wv=saWv[k][q], hv=shv[q];
                    a0+=wv.x*hv.x; a1+=wv.y*hv.y; a2+=wv.z*hv.z; a3+=wv.w*hv.w;
                }
                slog[k]=(a0+a1)+(a2+a3)+sab_s[k];
            }
        } else if (tid>=232 && tid<240){
            if (t<TT_-1)
                ((float*)sxv[pb^1])[tid-232] = a[((size_t)b*TT_+t)*8 + (tid-232)];
        }
        __syncthreads();
        // ---- P2 ----
        if (tid<50){
            float pi=spre[tid], pf=spre[50+tid], pg=spre[100+tid], po=spre[150+tid];
            float ig=fsig(pi);
            float fg=fsig(pf);
            float gg=ftanh(pg);
            float og=fsig(po);
            c = fg*c + ig*gg;
            ((float*)shv)[tid] = og*ftanh(c);
        } else if (tid>=224 && tid<227 && t>0){
            int k=tid-224;
            float l0=slog[0],l1=slog[1],l2=slog[2];
            float mx=fmaxf(l0,fmaxf(l1,l2));
            float e0=__expf(l0-mx),e1=__expf(l1-mx),e2=__expf(l2-mx);
            float inv=__fdividef(1.f, e0+e1+e2);
            float mine=(k==0)?e0:((k==1)?e1:e2);
            alpha[((size_t)b*TT_+t-1)*3+k]=mine*inv;
        }
        __syncthreads();
    }
    // final alpha (t = T-1) from h_{T-1}
    if (tid>=224 && tid<227){
        int k=tid-224;
        float lg[3];
#pragma unroll
        for (int kk=0;kk<3;kk++){
            float a0=0,a1=0,a2=0,a3=0;
#pragma unroll
            for (int q=0;q<13;q++){
                float4 wv=saWv[kk][q], hv=shv[q];
                a0+=wv.x*hv.x; a1+=wv.y*hv.y; a2+=wv.z*hv.z; a3+=wv.w*hv.w;
            }
            lg[kk]=(a0+a1)+(a2+a3)+sab_s[kk];
        }
        float mx=fmaxf(lg[0],fmaxf(lg[1],lg[2]));
        float e0=__expf(lg[0]-mx),e1=__expf(lg[1]-mx),e2=__expf(lg[2]-mx);
        float inv=__fdividef(1.f, e0+e1+e2);
        float mine=(k==0)?e0:((k==1)?e1:e2);
        alpha[((size_t)b*TT_+TT_-1)*3+k]=mine*inv;
    }
}

// ======================== Kalman forward: table-driven uniform phases ==============
// Per-warp smem state offsets (floats, < 512 so they fit 9-bit table fields)
#define KO_AM   0
#define KO_BM   16
#define KO_CM   52
#define KO_SIG  84
#define KO_SIGP 100
#define KO_PADJ 116
#define KO_CTC  132
#define KO_N    148
#define KO_NADJ 164
#define KO_T2   180
#define KO_JT   196
#define KO_W    212
#define KO_MU   244
#define KO_MUP  248
#define KO_RES  252
#define KO_AT   260
#define KO_UT   268
#define KO_SC   280
#define KO_ONE  284
#define KO_ZERO 285
#define KO_IRC  286
#define KO_QNS  287
#define KWSZ    288

__device__ __forceinline__ uint32_t kenc(int ia,int ib,int ic,int neg){
    return (uint32_t)ia | ((uint32_t)ib<<9) | ((uint32_t)ic<<18) | ((uint32_t)neg<<31);
}

// Uniform signed triple-product accumulation over smem with per-lane tables.
template<int T>
__device__ __forceinline__ float phase_dot(const float* __restrict__ s,
                                           const uint32_t* __restrict__ tab, int ln){
    float a0=0.f, a1=0.f;
#pragma unroll
    for (int m=0;m<T;m++){
        uint32_t e = tab[m*32+ln];
        float v = s[e & 511u] * s[(e>>9) & 511u] * s[(e>>18) & 511u];
        float sg = __int_as_float(0x3f800000u | (e & 0x80000000u));
        if (m & 1) a1 = fmaf(v, sg, a1); else a0 = fmaf(v, sg, a0);
    }
    return a0 + a1;
}

__global__ __launch_bounds__(64)
void kf_forward(const float* __restrict__ alpha, const float* __restrict__ a,
                const float* __restrict__ a_init, const float* __restrict__ u_ext,
                const float* __restrict__ Ag, const float* __restrict__ Bg,
                const float* __restrict__ Cg,
                float* __restrict__ mu_p_g, float* __restrict__ mu_f_g,
                float* __restrict__ Jg)
{
    __shared__ float sCat[3*84];            // [k][A(16);B(36);C(32)]
    __shared__ float wsm[2][KWSZ];
    __shared__ uint32_t tb2[16*32], tb3[8*32], tb4[8*32], tb5[8*32], tb6[6*32];
    __shared__ uint32_t aux2[32], aux3[32], aux4[32], aux5[32], aux6[32];

    const float ir = 1.f/0.03f;
    int w = threadIdx.x>>5, ln = threadIdx.x&31;
    int b = blockIdx.x*2 + w;

    // stage concatenated mixture matrices: sCat[k*84 + f]
    for (int i=threadIdx.x;i<48;i+=64){ int k=i/16, f=i%16;  sCat[k*84+f]      = Ag[i]; }
    for (int i=threadIdx.x;i<108;i+=64){int k=i/36, f=i%36;  sCat[k*84+16+f]   = Bg[i]; }
    for (int i=threadIdx.x;i<96;i+=64){ int k=i/32, f=i%32;  sCat[k*84+52+f]   = Cg[i]; }
    // constants + state init (both warps)
    if (threadIdx.x<2){
        float* s0 = wsm[threadIdx.x];
        s0[KO_ONE]=1.f; s0[KO_ZERO]=0.f; s0[KO_IRC]=ir; s0[KO_QNS]=0.08f;
        for (int i=0;i<16;i++) s0[KO_SIG+i]=0.f;
        for (int i=0;i<4;i++)  s0[KO_MU+i]=0.f;
    }

    // ---- build tables (thread 0) ----
    if (threadIdx.x==0){
        const uint32_t ZT = kenc(KO_ZERO,KO_ZERO,KO_ZERO,0);
        const int PI_[10]={0,0,0,0,1,1,1,2,2,3};
        const int PJ_[10]={0,1,2,3,1,2,3,2,3,3};
        const int P3p[6][3]={{0,1,2},{0,2,1},{1,0,2},{1,2,0},{2,0,1},{2,1,0}};
        const int SG3[6]={0,1,1,0,0,1};
        // PH2 (16 terms): Sig_p | mu_p | CtC/r
        for (int l=0;l<32;l++){
            uint32_t init=KO_ZERO, out=KO_ZERO, mir=KO_ZERO;
            for (int m=0;m<16;m++) tb2[m*32+l]=ZT;
            if (l<16){
                int i=l>>2, j=l&3;
                for (int m=0;m<16;m++){
                    int k=m>>2, q=m&3;
                    tb2[m*32+l]=kenc(KO_AM+i*4+k, KO_SIG+k*4+q, KO_AM+j*4+q, 0);
                }
                init=(i==j)?KO_QNS:KO_ZERO; out=KO_SIGP+l; mir=out;
            } else if (l<20){
                int r=l-16;
                for (int m=0;m<4;m++)  tb2[m*32+l]=kenc(KO_AM+r*4+m, KO_MU+m, KO_ONE, 0);
                for (int m=4;m<13;m++) tb2[m*32+l]=kenc(KO_BM+r*9+(m-4), KO_UT+(m-4), KO_ONE, 0);
                out=KO_MUP+r; mir=out;
            } else if (l<30){
                int p=l-20, pi=PI_[p], pj=PJ_[p];
                for (int m=0;m<8;m++) tb2[m*32+l]=kenc(KO_CM+m*4+pi, KO_CM+m*4+pj, KO_IRC, 0);
                out=KO_CTC+pi*4+pj; mir=KO_CTC+pj*4+pi;
            }
            aux2[l]= init | (out<<9) | (mir<<18);
        }
        // PH3 (8): PADJ(SIGP) | T2 = Sig_f_prev * Am^T
        for (int l=0;l<32;l++){
            for (int m=0;m<8;m++) tb3[m*32+l]=ZT;
            uint32_t out=KO_ZERO;
            if (l<16){
                int r=l>>2, c=l&3;
                int rr[3], cc[3]; int p=0;
                for (int k=0;k<4;k++) if (k!=c) rr[p++]=k;
                p=0;
                for (int k=0;k<4;k++) if (k!=r) cc[p++]=k;
                int base=(r+c)&1;
                for (int m=0;m<6;m++){
                    tb3[m*32+l]=kenc(KO_SIGP+rr[0]*4+cc[P3p[m][0]],
                                     KO_SIGP+rr[1]*4+cc[P3p[m][1]],
                                     KO_SIGP+rr[2]*4+cc[P3p[m][2]], SG3[m]^base);
                }
                out=KO_PADJ+l;
            } else {
                int l2=l-16, i=l2>>2, j=l2&3;
                for (int m=0;m<4;m++) tb3[m*32+l]=kenc(KO_SIG+i*4+m, KO_AM+j*4+m, KO_ONE, 0);
                out=KO_T2+l2;
            }
            aux3[l]=out;
        }
        // PH4 (8): JT = T2*PADJ | res | detP
        for (int l=0;l<32;l++){
            for (int m=0;m<8;m++) tb4[m*32+l]=ZT;
            uint32_t out=KO_ZERO;
            if (l<16){
                int i=l>>2, j=l&3;
                for (int m=0;m<4;m++) tb4[m*32+l]=kenc(KO_T2+i*4+m, KO_PADJ+m*4+j, KO_ONE, 0);
                out=KO_JT+l;
            } else if (l<24){
                int cc=l-16;
                tb4[0*32+l]=kenc(KO_AT+cc, KO_ONE, KO_ONE, 0);
                for (int m=1;m<5;m++) tb4[m*32+l]=kenc(KO_CM+cc*4+(m-1), KO_MUP+(m-1), KO_ONE, 1);
                out=KO_RES+cc;
            } else if (l==24){
                for (int m=0;m<4;m++) tb4[m*32+l]=kenc(KO_SIGP+m, KO_PADJ+m*4, KO_ONE, 0);
                out=KO_SC+0;
            }
            aux4[l]=out;
        }
        // PH5 (8): N = PADJ + detP*CtC | w = C^T res
        for (int l=0;l<32;l++){
            for (int m=0;m<8;m++) tb5[m*32+l]=ZT;
            uint32_t out=KO_ZERO;
            if (l<16){
                tb5[0*32+l]=kenc(KO_PADJ+l, KO_ONE, KO_ONE, 0);
                tb5[1*32+l]=kenc(KO_SC+0, KO_CTC+l, KO_ONE, 0);
                out=KO_N+l;
            } else if (l<20){
                int i=l-16;
                for (int m=0;m<8;m++) tb5[m*32+l]=kenc(KO_CM+m*4+i, KO_RES+m, KO_ONE, 0);
                out=KO_W+i;
            }
            aux5[l]=out;
        }
        // PH6 (6): NADJ(N)
        for (int l=0;l<32;l++){
            for (int m=0;m<6;m++) tb6[m*32+l]=ZT;
            uint32_t out=KO_ZERO;
            if (l<16){
                int r=l>>2, c=l&3;
                int rr[3], cc[3]; int p=0;
                for (int k=0;k<4;k++) if (k!=c) rr[p++]=k;
                p=0;
                for (int k=0;k<4;k++) if (k!=r) cc[p++]=k;
                int base=(r+c)&1;
                for (int m=0;m<6;m++){
                    tb6[m*32+l]=kenc(KO_N+rr[0]*4+cc[P3p[m][0]],
                                     KO_N+rr[1]*4+cc[P3p[m][1]],
                                     KO_N+rr[2]*4+cc[P3p[m][2]], SG3[m]^base);
                }
                out=KO_NADJ+l;
            }
            aux6[l]=out;
        }
    }
    __syncthreads();
    float* s = wsm[w];

    // prefetch t=0 inputs
    float r_al=0.f, r_a=0.f, r_u=0.f, r_ap=0.f;
    if (ln<3)            r_al = alpha[(size_t)b*TT_*3 + ln];
    if (ln>=4 && ln<12){ r_a  = a[(size_t)b*TT_*8 + (ln-4)]; r_ap = a_init[ln-4]; }
    if (ln==12)          r_u  = u_ext[(size_t)b*TT_];

    const uint32_t a2 = aux2[ln], a3 = aux3[ln], a4 = aux4[ln], a5 = aux5[ln], a6 = aux6[ln];

    for (int t=0;t<TT_;t++){
        size_t bt = (size_t)b*TT_ + t;
        // ---- PH1: alpha via shfl; mix 84 elems (uniform); publish a_t/u_t; prefetch ----
        float al0=__shfl_sync(0xffffffffu, r_al, 0);
        float al1=__shfl_sync(0xffffffffu, r_al, 1);
        float al2=__shfl_sync(0xffffffffu, r_al, 2);
#pragma unroll
        for (int it=0;it<3;it++){
            int f = ln + it*32;
            if (f<84)
                s[f] = al0*sCat[f] + al1*sCat[84+f] + al2*sCat[168+f];
        }
        if (ln>=4 && ln<12){ s[KO_AT+ln-4]=r_a; s[KO_UT+ln-4]=r_ap; r_ap=r_a; }
        if (ln==12) s[KO_UT+8]=r_u;
        if (t+1<TT_){
            if (ln<3)            r_al = alpha[(bt+1)*3+ln];
            if (ln>=4 && ln<12)  r_a  = a[(bt+1)*8 + (ln-4)];
            if (ln==12)          r_u  = u_ext[bt+1];
        }
        __syncwarp();
        // ---- PH2: Sig_p | mu_p | CtC (uniform 16-term) ----
        {
            float acc = phase_dot<16>(s, tb2, ln) + s[a2 & 511u];
            s[(a2>>9) & 511u] = acc;
            s[(a2>>18) & 511u] = acc;
            if (t==0){
                if (ln<16) s[KO_SIGP+ln] = ((ln>>2)==(ln&3))? 20.f : 0.f;
                else if (ln<20) s[KO_MUP+ln-16]=0.f;
            }
        }
        __syncwarp();
        // ---- PH3: PADJ | T2 ----
        s[a3] = phase_dot<8>(s, tb3, ln);
        __syncwarp();
        // ---- PH4: JT | res | detP ----
        s[a4] = phase_dot<8>(s, tb4, ln);
        __syncwarp();
        // ---- PH5: N | w ----
        s[a5] = phase_dot<8>(s, tb5, ln);
        __syncwarp();
        // ---- PH6: NADJ ; J store (lanes 16-31, t>0) ----
        s[a6] = phase_dot<6>(s, tb6, ln);
        if (ln>=16 && t>0){
            int l2=ln-16;
            Jg[(bt-1)*16 + l2] = __fdividef(s[KO_JT+l2], s[KO_SC+0]);
        }
        __syncwarp();
        // ---- PH7: Sig_f ; mu_f ; stores ----
        if (ln<16){
            float dn = s[KO_N+0]*s[KO_NADJ+0] + s[KO_N+1]*s[KO_NADJ+4]
                     + s[KO_N+2]*s[KO_NADJ+8] + s[KO_N+3]*s[KO_NADJ+12];
            float sc = __fdividef(s[KO_SC+0], dn);
            s[KO_SIG+ln] = s[KO_NADJ+ln]*sc;
        } else if (ln<20){
            int r=ln-16;
            float dn = s[KO_N+0]*s[KO_NADJ+0] + s[KO_N+1]*s[KO_NADJ+4]
                     + s[KO_N+2]*s[KO_NADJ+8] + s[KO_N+3]*s[KO_NADJ+12];
            float sc = __fdividef(s[KO_SC+0], dn);
            float acc=0.f;
#pragma unroll
            for (int k=0;k<4;k++) acc += s[KO_NADJ+r*4+k]*s[KO_W+k];
            float v = s[KO_MUP+r] + acc*sc*ir;
            s[KO_MU+r]=v;
            mu_f_g[bt*4+r]=v;
        } else if (ln<24){
            mu_p_g[bt*4+ln-20]=s[KO_MUP+ln-20];
        }
        __syncwarp();
    }
}

// ---------------- backward mu_smooth recursion (4 lanes per batch, prefetched) ------
__global__ __launch_bounds__(32)
void smooth_kernel(const float* __restrict__ mu_f, const float* __restrict__ mu_p,
                   const float* __restrict__ Jg, float* __restrict__ mus)
{
    int tid = threadIdx.x;
    int g = blockIdx.x*8 + (tid>>2);
    int i = tid & 3;
    size_t base = (size_t)g*TT_;
    float v = mu_f[(base+TT_-1)*4 + i];
    mus[(base+TT_-1)*4 + i] = v;
    unsigned gb = tid & ~3u;
    float4 Jr = *(const float4*)&Jg[(base+TT_-2)*16 + i*4];
    float mf = mu_f[(base+TT_-2)*4 + i];
    float mp = mu_p[(base+TT_-1)*4 + i];
    for (int t=TT_-2; t>=0; t--){
        float4 Jn; float mfn=0.f, mpn=0.f;
        if (t>0){
            Jn  = *(const float4*)&Jg[(base+t-1)*16 + i*4];
            mfn = mu_f[(base+t-1)*4 + i];
            mpn = mu_p[(base+t)*4 + i];
        } else { Jn = Jr; }
        float mi = v - mp;
        float m0=__shfl_sync(0xffffffffu, mi, gb+0);
        float m1=__shfl_sync(0xffffffffu, mi, gb+1);
        float m2=__shfl_sync(0xffffffffu, mi, gb+2);
        float m3=__shfl_sync(0xffffffffu, mi, gb+3);
        v = mf + Jr.x*m0 + Jr.y*m1 + Jr.z*m2 + Jr.w*m3;
        mus[(base+t)*4+i]=v;
        Jr=Jn; mf=mfn; mp=mpn;
    }
}

// ---------------- a_hat = C_mix mu_smooth -------------------------------------------
__global__ void ahat_kernel(const float* __restrict__ alpha, const float* __restrict__ mus,
                            const float* __restrict__ Cg, float* __restrict__ ahat)
{
    int idx = blockIdx.x*blockDim.x + threadIdx.x;
    if (idx >= NROWS) return;
    float a0=alpha[(size_t)idx*3+0], a1=alpha[(size_t)idx*3+1], a2=alpha[(size_t)idx*3+2];
    float4 mu = *(const float4*)&mus[(size_t)idx*4];
    float mv[4]={mu.x,mu.y,mu.z,mu.w};
#pragma unroll
    for (int r=0;r<8;r++){
        float v=0.f;
#pragma unroll
        for (int j=0;j<4;j++){
            float cm = a0*__ldg(&Cg[r*4+j]) + a1*__ldg(&Cg[32+r*4+j]) + a2*__ldg(&Cg[64+r*4+j]);
            v += cm*mv[j];
        }
        ahat[(size_t)idx*8+r]=v;
    }
}

// ---------------- decoder layer 1: d1 = tanh(ahat @ W^T + b) (K=8) ------------------
__global__ __launch_bounds__(256)
void dec1_kernel(const float* __restrict__ ahat, const float* __restrict__ W,
                 const float* __restrict__ bvec, float* __restrict__ out)
{
    __shared__ float sa[16][8];
    int tid = threadIdx.x;
    int r0 = blockIdx.x*16;
    if (tid<128) sa[tid>>3][tid&7] = ahat[(size_t)r0*8 + tid];
    int n = tid & 127;
    float w[8];
#pragma unroll
    for (int j=0;j<8;j++) w[j]=W[n*8+j];
    float bb=bvec[n];
    __syncthreads();
    int half = tid>>7;
#pragma unroll
    for (int q=0;q<8;q++){
        int rl = half*8+q;
        float s=bb;
#pragma unroll
        for (int j=0;j<8;j++) s += sa[rl][j]*w[j];
        out[(size_t)(r0+rl)*128 + n] = ftanh(s);
    }
}

// ---------------- launcher ----------------------------------------------------------
extern "C" void kernel_launch(void* const* d_in, const int* in_sizes, int n_in,
                              void* d_out, int out_size)
{
    const float* x       = (const float*)d_in[0];
    const float* m       = (const float*)d_in[1];
    const float* u_ext   = (const float*)d_in[2];
    const float* eps     = (const float*)d_in[3];
    const float* enc_W1  = (const float*)d_in[4];
    const float* enc_b1  = (const float*)d_in[5];
    const float* enc_W2  = (const float*)d_in[6];
    const float* enc_b2  = (const float*)d_in[7];
    const float* W_mean  = (const float*)d_in[8];
    const float* b_mean  = (const float*)d_in[9];
    const float* Amat    = (const float*)d_in[10];
    const float* Bmat    = (const float*)d_in[11];
    const float* Cmat    = (const float*)d_in[12];
    const float* a_init  = (const float*)d_in[13];
    const float* lstm_Wih= (const float*)d_in[14];
    const float* lstm_Whh= (const float*)d_in[15];
    const float* lstm_bih= (const float*)d_in[16];
    const float* lstm_bhh= (const float*)d_in[17];
    const float* alpha_W = (const float*)d_in[18];
    const float* alpha_b = (const float*)d_in[19];
    const float* dec_W1  = (const float*)d_in[20];
    const float* dec_b1  = (const float*)d_in[21];
    const float* dec_W2  = (const float*)d_in[22];
    const float* dec_b2  = (const float*)d_in[23];
    const float* gen_W   = (const float*)d_in[24];
    const float* gen_b   = (const float*)d_in[25];

    float *p_buf1,*p_buf2,*p_a,*p_alpha,*p_mup,*p_muf,*p_J,*p_mus,*p_ahat;
    cudaGetSymbolAddress((void**)&p_buf1,  g_buf1);
    cudaGetSymbolAddress((void**)&p_buf2,  g_buf2);
    cudaGetSymbolAddress((void**)&p_a,     g_a);
    cudaGetSymbolAddress((void**)&p_alpha, g_alpha);
    cudaGetSymbolAddress((void**)&p_mup,   g_mup);
    cudaGetSymbolAddress((void**)&p_muf,   g_muf);
    cudaGetSymbolAddress((void**)&p_J,     g_J);
    cudaGetSymbolAddress((void**)&p_mus,   g_mus);
    cudaGetSymbolAddress((void**)&p_ahat,  g_ahat);

    // encoder (tf32 tensor cores)
    tgemm128<1,true ><<<NROWS/128,256>>>(x, m, enc_W1, enc_b1, p_buf1, 256);
    tgemm128<1,false><<<NROWS/128,256>>>(p_buf1, nullptr, enc_W2, enc_b2, p_buf2, 128);
    enc3_kernel<<<NROWS/32,256>>>(p_buf2, W_mean, b_mean, eps, p_a);
    // LSTM -> alpha
    lstm_kernel<<<BSZ,256>>>(p_a, a_init, lstm_Wih, lstm_Whh, lstm_bih, lstm_bhh,
                             alpha_W, alpha_b, p_alpha);
    // Kalman forward (+ fused smoother gains J), table-driven uniform phases
    kf_forward<<<BSZ/2,64>>>(p_alpha, p_a, a_init, u_ext, Amat, Bmat, Cmat,
                             p_mup, p_muf, p_J);
    // backward mu recursion
    smooth_kernel<<<32,32>>>(p_muf, p_mup, p_J, p_mus);
    ahat_kernel<<<NROWS/256,256>>>(p_alpha, p_mus, Cmat, p_ahat);
    // decoder (tf32 tensor cores)
    dec1_kernel<<<NROWS/16,256>>>(p_ahat, dec_W1, dec_b1, p_buf1);
    tgemm128<1,false><<<NROWS/128,256>>>(p_buf1, nullptr, dec_W2, dec_b2, p_buf2, 128);
    tgemm128<2,false><<<NROWS/128,256>>>(p_buf2, nullptr, gen_W, gen_b, (float*)d_out, 128);
    (void)in_sizes; (void)n_in; (void)out_size;
}

// round 8
// speedup vs baseline: 1.1937x; 1.0547x over previous
#include <cuda_runtime.h>
#include <math.h>
#include <stdint.h>

#define BSZ 256
#define TT_ 512
#define ADIM 8
#define ZDIM 4
#define KMIX 3
#define HL 50
#define HID 128
#define NROWS (BSZ*TT_)

// ---------------- scratch (static __device__; cudaMalloc forbidden) ----------------
__device__ float g_buf1[NROWS*HID];
__device__ float g_buf2[NROWS*HID];
__device__ float g_a[NROWS*ADIM];
__device__ float g_alpha[NROWS*KMIX];
__device__ float g_mup[NROWS*ZDIM];
__device__ float g_muf[NROWS*ZDIM];
__device__ float g_J[NROWS*ZDIM*ZDIM];
__device__ float g_ahat[NROWS*ADIM];

// ---------------- fast activations ----------------
__device__ __forceinline__ float fsig(float x){
    return __fdividef(1.f, 1.f + __expf(-x));
}
__device__ __forceinline__ float ftanh(float x){
    float xc = fminf(fmaxf(x, -15.f), 15.f);
    float t = __expf(2.f*xc);
    return __fdividef(t-1.f, t+1.f);
}

template<int ACT>
__device__ __forceinline__ float actf(float v){
    if (ACT == 1) return ftanh(v);
    if (ACT == 2) return fsig(v);
    return v;
}

// ---------------- tf32 helpers ------------------------------------------------------
__device__ __forceinline__ uint32_t tf32_of(float x){
    uint32_t r;
    asm("cvt.rna.tf32.f32 %0, %1;" : "=r"(r) : "f"(x));
    return r;
}
__device__ __forceinline__ void mma_tf32(float* d, const uint32_t* a, const uint32_t* b){
    asm volatile("mma.sync.aligned.m16n8k8.row.col.f32.tf32.tf32.f32 "
        "{%0,%1,%2,%3},{%4,%5,%6,%7},{%8,%9},{%0,%1,%2,%3};"
        : "+f"(d[0]),"+f"(d[1]),"+f"(d[2]),"+f"(d[3])
        : "r"(a[0]),"r"(a[1]),"r"(a[2]),"r"(a[3]),"r"(b[0]),"r"(b[1]));
}

// ---------------- tf32 tensor-core GEMM: C[M,128] = act(A[M,K] @ W[128,K]^T + b) ----
template<int ACT, bool CONCAT>
__global__ __launch_bounds__(256)
void tgemm128(const float* __restrict__ A0, const float* __restrict__ A1,
              const float* __restrict__ W, const float* __restrict__ bias,
              float* __restrict__ C, int K)
{
    __shared__ __align__(16) float sA[128][36];
    __shared__ __align__(16) float sW[128][36];
    const int tid = threadIdx.x;
    const int wid = tid>>5, ln = tid&31;
    const int g = ln>>2, q = ln&3;
    const int wm = (wid&3)*32;
    const int wn = (wid>>2)*64;
    const int row0 = blockIdx.x*128;

    float d[2][8][4];
#pragma unroll
    for (int mt=0;mt<2;mt++)
#pragma unroll
        for (int nt=0;nt<8;nt++)
#pragma unroll
            for (int i=0;i<4;i++) d[mt][nt][i]=0.f;

    for (int k0=0;k0<K;k0+=32){
        __syncthreads();
#pragma unroll
        for (int it=0;it<4;it++){
            int idx = tid + it*256;
            int r = idx>>3, c4 = (idx&7)*4;
            const float* src;
            if (CONCAT){
                int gk = k0 + c4;
                src = (gk<128)? (A0+(size_t)(row0+r)*128+gk)
                              : (A1+(size_t)(row0+r)*128+(gk-128));
            } else {
                src = A0+(size_t)(row0+r)*K + k0 + c4;
            }
            float4 v = *(const float4*)src;
            float4 o;
            o.x=__uint_as_float(tf32_of(v.x)); o.y=__uint_as_float(tf32_of(v.y));
            o.z=__uint_as_float(tf32_of(v.z)); o.w=__uint_as_float(tf32_of(v.w));
            *(float4*)&sA[r][c4] = o;
        }
#pragma unroll
        for (int it=0;it<4;it++){
            int idx = tid + it*256;
            int n = idx>>3, c4 = (idx&7)*4;
            float4 v = *(const float4*)(W+(size_t)n*K + k0 + c4);
            float4 o;
            o.x=__uint_as_float(tf32_of(v.x)); o.y=__uint_as_float(tf32_of(v.y));
            o.z=__uint_as_float(tf32_of(v.z)); o.w=__uint_as_float(tf32_of(v.w));
            *(float4*)&sW[n][c4] = o;
        }
        __syncthreads();
#pragma unroll
        for (int kk=0;kk<32;kk+=8){
            uint32_t af[2][4];
#pragma unroll
            for (int mt=0;mt<2;mt++){
                int mr = wm + mt*16;
                af[mt][0]=__float_as_uint(sA[mr+g  ][kk+q  ]);
                af[mt][1]=__float_as_uint(sA[mr+g+8][kk+q  ]);
                af[mt][2]=__float_as_uint(sA[mr+g  ][kk+q+4]);
                af[mt][3]=__float_as_uint(sA[mr+g+8][kk+q+4]);
            }
            uint32_t bf[8][2];
#pragma unroll
            for (int nt=0;nt<8;nt++){
                int nc = wn + nt*8 + g;
                bf[nt][0]=__float_as_uint(sW[nc][kk+q  ]);
                bf[nt][1]=__float_as_uint(sW[nc][kk+q+4]);
            }
#pragma unroll
            for (int mt=0;mt<2;mt++)
#pragma unroll
                for (int nt=0;nt<8;nt++)
                    mma_tf32(d[mt][nt], af[mt], bf[nt]);
        }
    }
#pragma unroll
    for (int mt=0;mt<2;mt++){
        int r_top = row0 + wm + mt*16 + g;
#pragma unroll
        for (int nt=0;nt<8;nt++){
            int col = wn + nt*8 + 2*q;
            float b0v = bias[col], b1v = bias[col+1];
            float2 o0, o1;
            o0.x = actf<ACT>(d[mt][nt][0]+b0v);
            o0.y = actf<ACT>(d[mt][nt][1]+b1v);
            o1.x = actf<ACT>(d[mt][nt][2]+b0v);
            o1.y = actf<ACT>(d[mt][nt][3]+b1v);
            *(float2*)&C[(size_t)r_top*128 + col]     = o0;
            *(float2*)&C[(size_t)(r_top+8)*128 + col] = o1;
        }
    }
}

// ---------------- GEMM2 + enc3 fused: a = tanh(A@W2'+b2) @ Wm' + bm + eps ----------
// h2 stays in registers; per-warp partial dots reduced via shfl_xor over q-lanes,
// wn-halves combined through padded smem. h2 never touches global memory.
__global__ __launch_bounds__(256)
void tgemm128_enc(const float* __restrict__ A0, const float* __restrict__ W,
                  const float* __restrict__ bias, const float* __restrict__ Wm,
                  const float* __restrict__ bm, const float* __restrict__ eps,
                  float* __restrict__ aout)
{
    __shared__ __align__(16) float sA[128][36];
    __shared__ __align__(16) float sW[128][36];
    __shared__ __align__(16) float sWm[8][128];
    __shared__ float sbm[8];
    const int K = 128;
    const int tid = threadIdx.x;
    const int wid = tid>>5, ln = tid&31;
    const int g = ln>>2, q = ln&3;
    const int wm = (wid&3)*32;
    const int wn = (wid>>2)*64;
    const int row0 = blockIdx.x*128;

    for (int i=tid;i<1024;i+=256) sWm[i>>7][i&127]=Wm[i];
    if (tid<8) sbm[tid]=bm[tid];

    float d[2][8][4];
#pragma unroll
    for (int mt=0;mt<2;mt++)
#pragma unroll
        for (int nt=0;nt<8;nt++)
#pragma unroll
            for (int i=0;i<4;i++) d[mt][nt][i]=0.f;

    for (int k0=0;k0<K;k0+=32){
        __syncthreads();
#pragma unroll
        for (int it=0;it<4;it++){
            int idx = tid + it*256;
            int r = idx>>3, c4 = (idx&7)*4;
            float4 v = *(const float4*)(A0+(size_t)(row0+r)*K + k0 + c4);
            float4 o;
            o.x=__uint_as_float(tf32_of(v.x)); o.y=__uint_as_float(tf32_of(v.y));
            o.z=__uint_as_float(tf32_of(v.z)); o.w=__uint_as_float(tf32_of(v.w));
            *(float4*)&sA[r][c4] = o;
        }
#pragma unroll
        for (int it=0;it<4;it++){
            int idx = tid + it*256;
            int n = idx>>3, c4 = (idx&7)*4;
            float4 v = *(const float4*)(W+(size_t)n*K + k0 + c4);
            float4 o;
            o.x=__uint_as_float(tf32_of(v.x)); o.y=__uint_as_float(tf32_of(v.y));
            o.z=__uint_as_float(tf32_of(v.z)); o.w=__uint_as_float(tf32_of(v.w));
            *(float4*)&sW[n][c4] = o;
        }
        __syncthreads();
#pragma unroll
        for (int kk=0;kk<32;kk+=8){
            uint32_t af[2][4];
#pragma unroll
            for (int mt=0;mt<2;mt++){
                int mr = wm + mt*16;
                af[mt][0]=__float_as_uint(sA[mr+g  ][kk+q  ]);
                af[mt][1]=__float_as_uint(sA[mr+g+8][kk+q  ]);
                af[mt][2]=__float_as_uint(sA[mr+g  ][kk+q+4]);
                af[mt][3]=__float_as_uint(sA[mr+g+8][kk+q+4]);
            }
            uint32_t bf[8][2];
#pragma unroll
            for (int nt=0;nt<8;nt++){
                int nc = wn + nt*8 + g;
                bf[nt][0]=__float_as_uint(sW[nc][kk+q  ]);
                bf[nt][1]=__float_as_uint(sW[nc][kk+q+4]);
            }
#pragma unroll
            for (int mt=0;mt<2;mt++)
#pragma unroll
                for (int nt=0;nt<8;nt++)
                    mma_tf32(d[mt][nt], af[mt], bf[nt]);
        }
    }
    __syncthreads();   // mainloop LDS complete before spart overwrites sA

    // spart[wgrp][row][9-padded 8]: reuse sA storage (4608 floats >= 2*128*9=2304)
    float* spart = &sA[0][0];
    int wgrp = wid>>2;
#pragma unroll
    for (int mt=0;mt<2;mt++){
#pragma unroll
        for (int half=0;half<2;half++){
            int row = wm + mt*16 + g + half*8;
            float p[8];
#pragma unroll
            for (int j=0;j<8;j++){
                float acc=0.f;
#pragma unroll
                for (int nt=0;nt<8;nt++){
                    int col = wn + nt*8 + 2*q;
                    float b0v = bias[col], b1v = bias[col+1];
                    float h0 = ftanh(d[mt][nt][half*2+0]+b0v);
                    float h1 = ftanh(d[mt][nt][half*2+1]+b1v);
                    acc += h0*sWm[j][col] + h1*sWm[j][col+1];
                }
                p[j]=acc;
            }
#pragma unroll
            for (int j=0;j<8;j++){
                p[j] += __shfl_xor_sync(0xffffffffu, p[j], 1);
                p[j] += __shfl_xor_sync(0xffffffffu, p[j], 2);
            }
            if (q==0){
#pragma unroll
                for (int j=0;j<8;j++)
                    spart[wgrp*1152 + row*9 + j] = p[j];
            }
        }
    }
    __syncthreads();
    // combine halves + bias + eps -> a
#pragma unroll
    for (int it=0;it<4;it++){
        int idx = tid + it*256;
        int row = idx>>3, j = idx&7;
        float v = spart[row*9+j] + spart[1152 + row*9 + j] + sbm[j]
                + eps[(size_t)(row0+row)*8 + j];
        aout[(size_t)(row0+row)*8 + j] = v;
    }
}

// ---------------- LSTM + alpha (R3/R5 version): 2 syncs/step, pipelined alpha ------
__global__ __launch_bounds__(256)
void lstm_kernel(const float* __restrict__ a, const float* __restrict__ a_init,
                 const float* __restrict__ Wih, const float* __restrict__ Whh,
                 const float* __restrict__ bih, const float* __restrict__ bhh,
                 const float* __restrict__ aW, const float* __restrict__ ab,
                 float* __restrict__ alpha)
{
    __shared__ __align__(16) float4 shv[13];      // h, padded to 52
    __shared__ __align__(16) float4 sxv[2][2];    // x_t, double buffered (8)
    __shared__ float spre[200];
    __shared__ __align__(16) float4 saWv[3][13];
    __shared__ float sab_s[3];
    __shared__ float slog[3];
    int tid=threadIdx.x; int b=blockIdx.x;

    float wih[8], whh[52], bsum=0.f, c=0.f;
    if (tid<200){
#pragma unroll
        for (int j=0;j<8;j++) wih[j]=Wih[tid*8+j];
#pragma unroll
        for (int j=0;j<50;j++) whh[j]=Whh[tid*50+j];
        whh[50]=0.f; whh[51]=0.f;
        bsum = bih[tid]+bhh[tid];
    }
    for (int i=tid;i<3*52;i+=256){
        int row=i/52, col=i%52;
        ((float*)saWv)[i] = (col<50)? aW[row*50+col] : 0.f;
    }
    if (tid<3) sab_s[tid]=ab[tid];
    for (int i=tid;i<52;i+=256) ((float*)shv)[i]=0.f;
    if (tid<8) ((float*)sxv)[tid]=a_init[tid];    // sxv[0] = a_init
    __syncthreads();

    for (int t=0;t<TT_;t++){
        int pb = t&1;
        // ---- P1 ----
        if (tid<200){
            const float4* xv = sxv[pb];
            float4 x0=xv[0], x1=xv[1];
            float a0 = bsum + wih[0]*x0.x + wih[4]*x1.x;
            float a1 = wih[1]*x0.y + wih[5]*x1.y;
            float a2 = wih[2]*x0.z + wih[6]*x1.z;
            float a3 = wih[3]*x0.w + wih[7]*x1.w;
#pragma unroll
            for (int q=0;q<13;q++){
                float4 hv=shv[q];
                a0 += whh[4*q+0]*hv.x;
                a1 += whh[4*q+1]*hv.y;
                a2 += whh[4*q+2]*hv.z;
                a3 += whh[4*q+3]*hv.w;
            }
            spre[tid]=(a0+a1)+(a2+a3);
        } else if (tid>=224 && tid<227){
            if (t>0){
                int k=tid-224;
                float a0=0,a1=0,a2=0,a3=0;
#pragma unroll
                for (int q=0;q<13;q++){
                    float4 wv=saWv[k][q], hv=shv[q];
                    a0+=wv.x*hv.x; a1+=wv.y*hv.y; a2+=wv.z*hv.z; a3+=wv.w*hv.w;
                }
                slog[k]=(a0+a1)+(a2+a3)+sab_s[k];
            }
        } else if (tid>=232 && tid<240){
            if (t<TT_-1)
                ((float*)sxv[pb^1])[tid-232] = a[((size_t)b*TT_+t)*8 + (tid-232)];
        }
        __syncthreads();
        // ---- P2 ----
        if (tid<50){
            float pi=spre[tid], pf=spre[50+tid], pg=spre[100+tid], po=spre[150+tid];
            float ig=fsig(pi);
            float fg=fsig(pf);
            float gg=ftanh(pg);
            float og=fsig(po);
            c = fg*c + ig*gg;
            ((float*)shv)[tid] = og*ftanh(c);
        } else if (tid>=224 && tid<227 && t>0){
            int k=tid-224;
            float l0=slog[0],l1=slog[1],l2=slog[2];
            float mx=fmaxf(l0,fmaxf(l1,l2));
            float e0=__expf(l0-mx),e1=__expf(l1-mx),e2=__expf(l2-mx);
            float inv=__fdividef(1.f, e0+e1+e2);
            float mine=(k==0)?e0:((k==1)?e1:e2);
            alpha[((size_t)b*TT_+t-1)*3+k]=mine*inv;
        }
        __syncthreads();
    }
    // final alpha (t = T-1) from h_{T-1}
    if (tid>=224 && tid<227){
        int k=tid-224;
        float lg[3];
#pragma unroll
        for (int kk=0;kk<3;kk++){
            float a0=0,a1=0,a2=0,a3=0;
#pragma unroll
            for (int q=0;q<13;q++){
                float4 wv=saWv[kk][q], hv=shv[q];
                a0+=wv.x*hv.x; a1+=wv.y*hv.y; a2+=wv.z*hv.z; a3+=wv.w*hv.w;
            }
            lg[kk]=(a0+a1)+(a2+a3)+sab_s[kk];
        }
        float mx=fmaxf(lg[0],fmaxf(lg[1],lg[2]));
        float e0=__expf(lg[0]-mx),e1=__expf(lg[1]-mx),e2=__expf(lg[2]-mx);
        float inv=__fdividef(1.f, e0+e1+e2);
        float mine=(k==0)?e0:((k==1)?e1:e2);
        alpha[((size_t)b*TT_+TT_-1)*3+k]=mine*inv;
    }
}

// ======================== Kalman forward: table-driven uniform phases ==============
#define KO_AM   0
#define KO_BM   16
#define KO_CM   52
#define KO_SIG  84
#define KO_SIGP 100
#define KO_PADJ 116
#define KO_CTC  132
#define KO_N    148
#define KO_NADJ 164
#define KO_T2   180
#define KO_JT   196
#define KO_W    212
#define KO_MU   244
#define KO_MUP  248
#define KO_RES  252
#define KO_AT   260
#define KO_UT   268
#define KO_SC   280
#define KO_ONE  284
#define KO_ZERO 285
#define KO_IRC  286
#define KO_QNS  287
#define KWSZ    288

__device__ __forceinline__ uint32_t kenc(int ia,int ib,int ic,int neg){
    return (uint32_t)ia | ((uint32_t)ib<<9) | ((uint32_t)ic<<18) | ((uint32_t)neg<<31);
}

template<int T>
__device__ __forceinline__ float phase_dot(const float* __restrict__ s,
                                           const uint32_t* __restrict__ tab, int ln){
    float a0=0.f, a1=0.f;
#pragma unroll
    for (int m=0;m<T;m++){
        uint32_t e = tab[m*32+ln];
        float v = s[e & 511u] * s[(e>>9) & 511u] * s[(e>>18) & 511u];
        float sg = __int_as_float(0x3f800000u | (e & 0x80000000u));
        if (m & 1) a1 = fmaf(v, sg, a1); else a0 = fmaf(v, sg, a0);
    }
    return a0 + a1;
}

__global__ __launch_bounds__(64)
void kf_forward(const float* __restrict__ alpha, const float* __restrict__ a,
                const float* __restrict__ a_init, const float* __restrict__ u_ext,
                const float* __restrict__ Ag, const float* __restrict__ Bg,
                const float* __restrict__ Cg,
                float* __restrict__ mu_p_g, float* __restrict__ mu_f_g,
                float* __restrict__ Jg)
{
    __shared__ float sCat[3*84];
    __shared__ float wsm[2][KWSZ];
    __shared__ uint32_t tb2[16*32], tb3[8*32], tb4[8*32], tb5[8*32], tb6[6*32];
    __shared__ uint32_t aux2[32], aux3[32], aux4[32], aux5[32], aux6[32];

    const float ir = 1.f/0.03f;
    int w = threadIdx.x>>5, ln = threadIdx.x&31;
    int b = blockIdx.x*2 + w;

    for (int i=threadIdx.x;i<48;i+=64){ int k=i/16, f=i%16;  sCat[k*84+f]      = Ag[i]; }
    for (int i=threadIdx.x;i<108;i+=64){int k=i/36, f=i%36;  sCat[k*84+16+f]   = Bg[i]; }
    for (int i=threadIdx.x;i<96;i+=64){ int k=i/32, f=i%32;  sCat[k*84+52+f]   = Cg[i]; }
    if (threadIdx.x<2){
        float* s0 = wsm[threadIdx.x];
        s0[KO_ONE]=1.f; s0[KO_ZERO]=0.f; s0[KO_IRC]=ir; s0[KO_QNS]=0.08f;
        for (int i=0;i<16;i++) s0[KO_SIG+i]=0.f;
        for (int i=0;i<4;i++)  s0[KO_MU+i]=0.f;
    }

    if (threadIdx.x==0){
        const uint32_t ZT = kenc(KO_ZERO,KO_ZERO,KO_ZERO,0);
        const int PI_[10]={0,0,0,0,1,1,1,2,2,3};
        const int PJ_[10]={0,1,2,3,1,2,3,2,3,3};
        const int P3p[6][3]={{0,1,2},{0,2,1},{1,0,2},{1,2,0},{2,0,1},{2,1,0}};
        const int SG3[6]={0,1,1,0,0,1};
        for (int l=0;l<32;l++){
            uint32_t init=KO_ZERO, out=KO_ZERO, mir=KO_ZERO;
            for (int m=0;m<16;m++) tb2[m*32+l]=ZT;
            if (l<16){
                int i=l>>2, j=l&3;
                for (int m=0;m<16;m++){
                    int k=m>>2, q=m&3;
                    tb2[m*32+l]=kenc(KO_AM+i*4+k, KO_SIG+k*4+q, KO_AM+j*4+q, 0);
                }
                init=(i==j)?KO_QNS:KO_ZERO; out=KO_SIGP+l; mir=out;
            } else if (l<20){
                int r=l-16;
                for (int m=0;m<4;m++)  tb2[m*32+l]=kenc(KO_AM+r*4+m, KO_MU+m, KO_ONE, 0);
                for (int m=4;m<13;m++) tb2[m*32+l]=kenc(KO_BM+r*9+(m-4), KO_UT+(m-4), KO_ONE, 0);
                out=KO_MUP+r; mir=out;
            } else if (l<30){
                int p=l-20, pi=PI_[p], pj=PJ_[p];
                for (int m=0;m<8;m++) tb2[m*32+l]=kenc(KO_CM+m*4+pi, KO_CM+m*4+pj, KO_IRC, 0);
                out=KO_CTC+pi*4+pj; mir=KO_CTC+pj*4+pi;
            }
            aux2[l]= init | (out<<9) | (mir<<18);
        }
        for (int l=0;l<32;l++){
            for (int m=0;m<8;m++) tb3[m*32+l]=ZT;
            uint32_t out=KO_ZERO;
            if (l<16){
                int r=l>>2, c=l&3;
                int rr[3], cc[3]; int p=0;
                for (int k=0;k<4;k++) if (k!=c) rr[p++]=k;
                p=0;
                for (int k=0;k<4;k++) if (k!=r) cc[p++]=k;
                int base=(r+c)&1;
                for (int m=0;m<6;m++){
                    tb3[m*32+l]=kenc(KO_SIGP+rr[0]*4+cc[P3p[m][0]],
                                     KO_SIGP+rr[1]*4+cc[P3p[m][1]],
                                     KO_SIGP+rr[2]*4+cc[P3p[m][2]], SG3[m]^base);
                }
                out=KO_PADJ+l;
            } else {
                int l2=l-16, i=l2>>2, j=l2&3;
                for (int m=0;m<4;m++) tb3[m*32+l]=kenc(KO_SIG+i*4+m, KO_AM+j*4+m, KO_ONE, 0);
                out=KO_T2+l2;
            }
            aux3[l]=out;
        }
        for (int l=0;l<32;l++){
            for (int m=0;m<8;m++) tb4[m*32+l]=ZT;
            uint32_t out=KO_ZERO;
            if (l<16){
                int i=l>>2, j=l&3;
                for (int m=0;m<4;m++) tb4[m*32+l]=kenc(KO_T2+i*4+m, KO_PADJ+m*4+j, KO_ONE, 0);
                out=KO_JT+l;
            } else if (l<24){
                int cc=l-16;
                tb4[0*32+l]=kenc(KO_AT+cc, KO_ONE, KO_ONE, 0);
                for (int m=1;m<5;m++) tb4[m*32+l]=kenc(KO_CM+cc*4+(m-1), KO_MUP+(m-1), KO_ONE, 1);
                out=KO_RES+cc;
            } else if (l==24){
                for (int m=0;m<4;m++) tb4[m*32+l]=kenc(KO_SIGP+m, KO_PADJ+m*4, KO_ONE, 0);
                out=KO_SC+0;
            }
            aux4[l]=out;
        }
        for (int l=0;l<32;l++){
            for (int m=0;m<8;m++) tb5[m*32+l]=ZT;
            uint32_t out=KO_ZERO;
            if (l<16){
                tb5[0*32+l]=kenc(KO_PADJ+l, KO_ONE, KO_ONE, 0);
                tb5[1*32+l]=kenc(KO_SC+0, KO_CTC+l, KO_ONE, 0);
                out=KO_N+l;
            } else if (l<20){
                int i=l-16;
                for (int m=0;m<8;m++) tb5[m*32+l]=kenc(KO_CM+m*4+i, KO_RES+m, KO_ONE, 0);
                out=KO_W+i;
            }
            aux5[l]=out;
        }
        for (int l=0;l<32;l++){
            for (int m=0;m<6;m++) tb6[m*32+l]=ZT;
            uint32_t out=KO_ZERO;
            if (l<16){
                int r=l>>2, c=l&3;
                int rr[3], cc[3]; int p=0;
                for (int k=0;k<4;k++) if (k!=c) rr[p++]=k;
                p=0;
                for (int k=0;k<4;k++) if (k!=r) cc[p++]=k;
                int base=(r+c)&1;
                for (int m=0;m<6;m++){
                    tb6[m*32+l]=kenc(KO_N+rr[0]*4+cc[P3p[m][0]],
                                     KO_N+rr[1]*4+cc[P3p[m][1]],
                                     KO_N+rr[2]*4+cc[P3p[m][2]], SG3[m]^base);
                }
                out=KO_NADJ+l;
            }
            aux6[l]=out;
        }
    }
    __syncthreads();
    float* s = wsm[w];

    float r_al=0.f, r_a=0.f, r_u=0.f, r_ap=0.f;
    if (ln<3)            r_al = alpha[(size_t)b*TT_*3 + ln];
    if (ln>=4 && ln<12){ r_a  = a[(size_t)b*TT_*8 + (ln-4)]; r_ap = a_init[ln-4]; }
    if (ln==12)          r_u  = u_ext[(size_t)b*TT_];

    const uint32_t a2 = aux2[ln], a3 = aux3[ln], a4 = aux4[ln], a5 = aux5[ln], a6 = aux6[ln];

    for (int t=0;t<TT_;t++){
        size_t bt = (size_t)b*TT_ + t;
        float al0=__shfl_sync(0xffffffffu, r_al, 0);
        float al1=__shfl_sync(0xffffffffu, r_al, 1);
        float al2=__shfl_sync(0xffffffffu, r_al, 2);
#pragma unroll
        for (int it=0;it<3;it++){
            int f = ln + it*32;
            if (f<84)
                s[f] = al0*sCat[f] + al1*sCat[84+f] + al2*sCat[168+f];
        }
        if (ln>=4 && ln<12){ s[KO_AT+ln-4]=r_a; s[KO_UT+ln-4]=r_ap; r_ap=r_a; }
        if (ln==12) s[KO_UT+8]=r_u;
        if (t+1<TT_){
            if (ln<3)            r_al = alpha[(bt+1)*3+ln];
            if (ln>=4 && ln<12)  r_a  = a[(bt+1)*8 + (ln-4)];
            if (ln==12)          r_u  = u_ext[bt+1];
        }
        __syncwarp();
        {
            float acc = phase_dot<16>(s, tb2, ln) + s[a2 & 511u];
            s[(a2>>9) & 511u] = acc;
            s[(a2>>18) & 511u] = acc;
            if (t==0){
                if (ln<16) s[KO_SIGP+ln] = ((ln>>2)==(ln&3))? 20.f : 0.f;
                else if (ln<20) s[KO_MUP+ln-16]=0.f;
            }
        }
        __syncwarp();
        s[a3] = phase_dot<8>(s, tb3, ln);
        __syncwarp();
        s[a4] = phase_dot<8>(s, tb4, ln);
        __syncwarp();
        s[a5] = phase_dot<8>(s, tb5, ln);
        __syncwarp();
        s[a6] = phase_dot<6>(s, tb6, ln);
        if (ln>=16 && t>0){
            int l2=ln-16;
            Jg[(bt-1)*16 + l2] = __fdividef(s[KO_JT+l2], s[KO_SC+0]);
        }
        __syncwarp();
        if (ln<16){
            float dn = s[KO_N+0]*s[KO_NADJ+0] + s[KO_N+1]*s[KO_NADJ+4]
                     + s[KO_N+2]*s[KO_NADJ+8] + s[KO_N+3]*s[KO_NADJ+12];
            float sc = __fdividef(s[KO_SC+0], dn);
            s[KO_SIG+ln] = s[KO_NADJ+ln]*sc;
        } else if (ln<20){
            int r=ln-16;
            float dn = s[KO_N+0]*s[KO_NADJ+0] + s[KO_N+1]*s[KO_NADJ+4]
                     + s[KO_N+2]*s[KO_NADJ+8] + s[KO_N+3]*s[KO_NADJ+12];
            float sc = __fdividef(s[KO_SC+0], dn);
            float acc=0.f;
#pragma unroll
            for (int k=0;k<4;k++) acc += s[KO_NADJ+r*4+k]*s[KO_W+k];
            float v = s[KO_MUP+r] + acc*sc*ir;
            s[KO_MU+r]=v;
            mu_f_g[bt*4+r]=v;
        } else if (ln<24){
            mu_p_g[bt*4+ln-20]=s[KO_MUP+ln-20];
        }
        __syncwarp();
    }
}

// ---------------- backward mu_smooth + ahat fused (4 lanes per batch) ---------------
// ahat = C_mix mu_smooth computed inline; mu_smooth never written to global.
__global__ __launch_bounds__(32)
void smooth_ahat_kernel(const float* __restrict__ mu_f, const float* __restrict__ mu_p,
                        const float* __restrict__ Jg, const float* __restrict__ alpha,
                        const float* __restrict__ Cg, float* __restrict__ ahat)
{
    __shared__ float sCg[96];
    int tid = threadIdx.x;
    for (int i=tid;i<96;i+=32) sCg[i]=Cg[i];
    __syncthreads();
    int g = blockIdx.x*8 + (tid>>2);
    int i = tid & 3;
    size_t base = (size_t)g*TT_;
    unsigned gb = tid & ~3u;

    float v = mu_f[(base+TT_-1)*4 + i];
    float alv = (i<3)? alpha[(base+TT_-1)*3 + i] : 0.f;

    // emit ahat for a given step: lane i writes outputs r=2i, 2i+1
    auto emit = [&](size_t btIdx, float vloc, float alLoc){
        float m0=__shfl_sync(0xffffffffu, vloc, gb+0);
        float m1=__shfl_sync(0xffffffffu, vloc, gb+1);
        float m2=__shfl_sync(0xffffffffu, vloc, gb+2);
        float m3=__shfl_sync(0xffffffffu, vloc, gb+3);
        float b0=__shfl_sync(0xffffffffu, alLoc, gb+0);
        float b1=__shfl_sync(0xffffffffu, alLoc, gb+1);
        float b2=__shfl_sync(0xffffffffu, alLoc, gb+2);
        float2 o;
#pragma unroll
        for (int e=0;e<2;e++){
            int r = i*2+e;
            float acc=0.f;
#pragma unroll
            for (int k=0;k<3;k++){
                const float* c = &sCg[k*32 + r*4];
                float dotv = c[0]*m0 + c[1]*m1 + c[2]*m2 + c[3]*m3;
                float bk = (k==0)?b0:((k==1)?b1:b2);
                acc += bk*dotv;
            }
            if (e==0) o.x=acc; else o.y=acc;
        }
        *(float2*)&ahat[btIdx*8 + i*2] = o;
    };

    emit(base+TT_-1, v, alv);

    float4 Jr = *(const float4*)&Jg[(base+TT_-2)*16 + i*4];
    float mf = mu_f[(base+TT_-2)*4 + i];
    float mp = mu_p[(base+TT_-1)*4 + i];
    alv = (i<3)? alpha[(base+TT_-2)*3 + i] : 0.f;

    for (int t=TT_-2; t>=0; t--){
        float4 Jn; float mfn=0.f, mpn=0.f, aln=0.f;
        if (t>0){
            Jn  = *(const float4*)&Jg[(base+t-1)*16 + i*4];
            mfn = mu_f[(base+t-1)*4 + i];
            mpn = mu_p[(base+t)*4 + i];
            aln = (i<3)? alpha[(base+t-1)*3 + i] : 0.f;
        } else { Jn = Jr; }
        float mi = v - mp;
        float m0=__shfl_sync(0xffffffffu, mi, gb+0);
        float m1=__shfl_sync(0xffffffffu, mi, gb+1);
        float m2=__shfl_sync(0xffffffffu, mi, gb+2);
        float m3=__shfl_sync(0xffffffffu, mi, gb+3);
        v = mf + Jr.x*m0 + Jr.y*m1 + Jr.z*m2 + Jr.w*m3;
        emit(base+t, v, alv);
        Jr=Jn; mf=mfn; mp=mpn; alv=aln;
    }
}

// ---------------- decoder layer 1: d1 = tanh(ahat @ W^T + b) (K=8) ------------------
__global__ __launch_bounds__(256)
void dec1_kernel(const float* __restrict__ ahat, const float* __restrict__ W,
                 const float* __restrict__ bvec, float* __restrict__ out)
{
    __shared__ float sa[16][8];
    int tid = threadIdx.x;
    int r0 = blockIdx.x*16;
    if (tid<128) sa[tid>>3][tid&7] = ahat[(size_t)r0*8 + tid];
    int n = tid & 127;
    float w[8];
#pragma unroll
    for (int j=0;j<8;j++) w[j]=W[n*8+j];
    float bb=bvec[n];
    __syncthreads();
    int half = tid>>7;
#pragma unroll
    for (int q=0;q<8;q++){
        int rl = half*8+q;
        float s=bb;
#pragma unroll
        for (int j=0;j<8;j++) s += sa[rl][j]*w[j];
        out[(size_t)(r0+rl)*128 + n] = ftanh(s);
    }
}

// ---------------- launcher ----------------------------------------------------------
extern "C" void kernel_launch(void* const* d_in, const int* in_sizes, int n_in,
                              void* d_out, int out_size)
{
    const float* x       = (const float*)d_in[0];
    const float* m       = (const float*)d_in[1];
    const float* u_ext   = (const float*)d_in[2];
    const float* eps     = (const float*)d_in[3];
    const float* enc_W1  = (const float*)d_in[4];
    const float* enc_b1  = (const float*)d_in[5];
    const float* enc_W2  = (const float*)d_in[6];
    const float* enc_b2  = (const float*)d_in[7];
    const float* W_mean  = (const float*)d_in[8];
    const float* b_mean  = (const float*)d_in[9];
    const float* Amat    = (const float*)d_in[10];
    const float* Bmat    = (const float*)d_in[11];
    const float* Cmat    = (const float*)d_in[12];
    const float* a_init  = (const float*)d_in[13];
    const float* lstm_Wih= (const float*)d_in[14];
    const float* lstm_Whh= (const float*)d_in[15];
    const float* lstm_bih= (const float*)d_in[16];
    const float* lstm_bhh= (const float*)d_in[17];
    const float* alpha_W = (const float*)d_in[18];
    const float* alpha_b = (const float*)d_in[19];
    const float* dec_W1  = (const float*)d_in[20];
    const float* dec_b1  = (const float*)d_in[21];
    const float* dec_W2  = (const float*)d_in[22];
    const float* dec_b2  = (const float*)d_in[23];
    const float* gen_W   = (const float*)d_in[24];
    const float* gen_b   = (const float*)d_in[25];

    float *p_buf1,*p_buf2,*p_a,*p_alpha,*p_mup,*p_muf,*p_J,*p_ahat;
    cudaGetSymbolAddress((void**)&p_buf1,  g_buf1);
    cudaGetSymbolAddress((void**)&p_buf2,  g_buf2);
    cudaGetSymbolAddress((void**)&p_a,     g_a);
    cudaGetSymbolAddress((void**)&p_alpha, g_alpha);
    cudaGetSymbolAddress((void**)&p_mup,   g_mup);
    cudaGetSymbolAddress((void**)&p_muf,   g_muf);
    cudaGetSymbolAddress((void**)&p_J,     g_J);
    cudaGetSymbolAddress((void**)&p_ahat,  g_ahat);

    // encoder: GEMM1, then GEMM2 with enc3 fused into epilogue (h2 stays on-chip)
    tgemm128<1,true ><<<NROWS/128,256>>>(x, m, enc_W1, enc_b1, p_buf1, 256);
    tgemm128_enc<<<NROWS/128,256>>>(p_buf1, enc_W2, enc_b2, W_mean, b_mean, eps, p_a);
    // LSTM -> alpha
    lstm_kernel<<<BSZ,256>>>(p_a, a_init, lstm_Wih, lstm_Whh, lstm_bih, lstm_bhh,
                             alpha_W, alpha_b, p_alpha);
    // Kalman forward (+ fused smoother gains J)  [user launch #4 -> ncu-profiled]
    kf_forward<<<BSZ/2,64>>>(p_alpha, p_a, a_init, u_ext, Amat, Bmat, Cmat,
                             p_mup, p_muf, p_J);
    // backward mu recursion + ahat fused (mu_smooth stays on-chip)
    smooth_ahat_kernel<<<32,32>>>(p_muf, p_mup, p_J, p_alpha, Cmat, p_ahat);
    // decoder
    dec1_kernel<<<NROWS/16,256>>>(p_ahat, dec_W1, dec_b1, p_buf1);
    tgemm128<1,false><<<NROWS/128,256>>>(p_buf1, nullptr, dec_W2, dec_b2, p_buf2, 128);
    tgemm128<2,false><<<NROWS/128,256>>>(p_buf2, nullptr, gen_W, gen_b, (float*)d_out, 128);
    (void)in_sizes; (void)n_in; (void)out_size;
}

// round 9
// speedup vs baseline: 1.8520x; 1.5514x over previous
#include <cuda_runtime.h>
#include <math.h>
#include <stdint.h>

#define BSZ 256
#define TT_ 512
#define ADIM 8
#define ZDIM 4
#define KMIX 3
#define HL 50
#define HID 128
#define NROWS (BSZ*TT_)

// ---------------- scratch (static __device__; cudaMalloc forbidden) ----------------
__device__ float g_buf1[NROWS*HID];
__device__ float g_buf2[NROWS*HID];
__device__ float g_a[NROWS*ADIM];
__device__ float g_alpha[NROWS*KMIX];
__device__ float g_mup[NROWS*ZDIM];
__device__ float g_muf[NROWS*ZDIM];
__device__ float g_J[NROWS*ZDIM*ZDIM];
__device__ float g_ahat[NROWS*ADIM];

// ---------------- fast activations ----------------
__device__ __forceinline__ float fsig(float x){
    return __fdividef(1.f, 1.f + __expf(-x));
}
__device__ __forceinline__ float ftanh(float x){
    float xc = fminf(fmaxf(x, -15.f), 15.f);
    float t = __expf(2.f*xc);
    return __fdividef(t-1.f, t+1.f);
}

template<int ACT>
__device__ __forceinline__ float actf(float v){
    if (ACT == 1) return ftanh(v);
    if (ACT == 2) return fsig(v);
    return v;
}

// ---------------- tf32 helpers ------------------------------------------------------
__device__ __forceinline__ uint32_t tf32_of(float x){
    uint32_t r;
    asm("cvt.rna.tf32.f32 %0, %1;" : "=r"(r) : "f"(x));
    return r;
}
__device__ __forceinline__ void mma_tf32(float* d, const uint32_t* a, const uint32_t* b){
    asm volatile("mma.sync.aligned.m16n8k8.row.col.f32.tf32.tf32.f32 "
        "{%0,%1,%2,%3},{%4,%5,%6,%7},{%8,%9},{%0,%1,%2,%3};"
        : "+f"(d[0]),"+f"(d[1]),"+f"(d[2]),"+f"(d[3])
        : "r"(a[0]),"r"(a[1]),"r"(a[2]),"r"(a[3]),"r"(b[0]),"r"(b[1]));
}

// ---------------- tf32 tensor-core GEMM: C[M,128] = act(A[M,K] @ W[128,K]^T + b) ----
template<int ACT, bool CONCAT>
__global__ __launch_bounds__(256)
void tgemm128(const float* __restrict__ A0, const float* __restrict__ A1,
              const float* __restrict__ W, const float* __restrict__ bias,
              float* __restrict__ C, int K)
{
    __shared__ __align__(16) float sA[128][36];
    __shared__ __align__(16) float sW[128][36];
    const int tid = threadIdx.x;
    const int wid = tid>>5, ln = tid&31;
    const int g = ln>>2, q = ln&3;
    const int wm = (wid&3)*32;
    const int wn = (wid>>2)*64;
    const int row0 = blockIdx.x*128;

    float d[2][8][4];
#pragma unroll
    for (int mt=0;mt<2;mt++)
#pragma unroll
        for (int nt=0;nt<8;nt++)
#pragma unroll
            for (int i=0;i<4;i++) d[mt][nt][i]=0.f;

    for (int k0=0;k0<K;k0+=32){
        __syncthreads();
#pragma unroll
        for (int it=0;it<4;it++){
            int idx = tid + it*256;
            int r = idx>>3, c4 = (idx&7)*4;
            const float* src;
            if (CONCAT){
                int gk = k0 + c4;
                src = (gk<128)? (A0+(size_t)(row0+r)*128+gk)
                              : (A1+(size_t)(row0+r)*128+(gk-128));
            } else {
                src = A0+(size_t)(row0+r)*K + k0 + c4;
            }
            float4 v = *(const float4*)src;
            float4 o;
            o.x=__uint_as_float(tf32_of(v.x)); o.y=__uint_as_float(tf32_of(v.y));
            o.z=__uint_as_float(tf32_of(v.z)); o.w=__uint_as_float(tf32_of(v.w));
            *(float4*)&sA[r][c4] = o;
        }
#pragma unroll
        for (int it=0;it<4;it++){
            int idx = tid + it*256;
            int n = idx>>3, c4 = (idx&7)*4;
            float4 v = *(const float4*)(W+(size_t)n*K + k0 + c4);
            float4 o;
            o.x=__uint_as_float(tf32_of(v.x)); o.y=__uint_as_float(tf32_of(v.y));
            o.z=__uint_as_float(tf32_of(v.z)); o.w=__uint_as_float(tf32_of(v.w));
            *(float4*)&sW[n][c4] = o;
        }
        __syncthreads();
#pragma unroll
        for (int kk=0;kk<32;kk+=8){
            uint32_t af[2][4];
#pragma unroll
            for (int mt=0;mt<2;mt++){
                int mr = wm + mt*16;
                af[mt][0]=__float_as_uint(sA[mr+g  ][kk+q  ]);
                af[mt][1]=__float_as_uint(sA[mr+g+8][kk+q  ]);
                af[mt][2]=__float_as_uint(sA[mr+g  ][kk+q+4]);
                af[mt][3]=__float_as_uint(sA[mr+g+8][kk+q+4]);
            }
            uint32_t bf[8][2];
#pragma unroll
            for (int nt=0;nt<8;nt++){
                int nc = wn + nt*8 + g;
                bf[nt][0]=__float_as_uint(sW[nc][kk+q  ]);
                bf[nt][1]=__float_as_uint(sW[nc][kk+q+4]);
            }
#pragma unroll
            for (int mt=0;mt<2;mt++)
#pragma unroll
                for (int nt=0;nt<8;nt++)
                    mma_tf32(d[mt][nt], af[mt], bf[nt]);
        }
    }
#pragma unroll
    for (int mt=0;mt<2;mt++){
        int r_top = row0 + wm + mt*16 + g;
#pragma unroll
        for (int nt=0;nt<8;nt++){
            int col = wn + nt*8 + 2*q;
            float b0v = bias[col], b1v = bias[col+1];
            float2 o0, o1;
            o0.x = actf<ACT>(d[mt][nt][0]+b0v);
            o0.y = actf<ACT>(d[mt][nt][1]+b1v);
            o1.x = actf<ACT>(d[mt][nt][2]+b0v);
            o1.y = actf<ACT>(d[mt][nt][3]+b1v);
            *(float2*)&C[(size_t)r_top*128 + col]     = o0;
            *(float2*)&C[(size_t)(r_top+8)*128 + col] = o1;
        }
    }
}

// ---------------- GEMM2 + enc3 fused: a = tanh(A@W2'+b2) @ Wm' + bm + eps ----------
__global__ __launch_bounds__(256)
void tgemm128_enc(const float* __restrict__ A0, const float* __restrict__ W,
                  const float* __restrict__ bias, const float* __restrict__ Wm,
                  const float* __restrict__ bm, const float* __restrict__ eps,
                  float* __restrict__ aout)
{
    __shared__ __align__(16) float sA[128][36];
    __shared__ __align__(16) float sW[128][36];
    __shared__ __align__(16) float sWm[8][128];
    __shared__ float sbm[8];
    const int K = 128;
    const int tid = threadIdx.x;
    const int wid = tid>>5, ln = tid&31;
    const int g = ln>>2, q = ln&3;
    const int wm = (wid&3)*32;
    const int wn = (wid>>2)*64;
    const int row0 = blockIdx.x*128;

    for (int i=tid;i<1024;i+=256) sWm[i>>7][i&127]=Wm[i];
    if (tid<8) sbm[tid]=bm[tid];

    float d[2][8][4];
#pragma unroll
    for (int mt=0;mt<2;mt++)
#pragma unroll
        for (int nt=0;nt<8;nt++)
#pragma unroll
            for (int i=0;i<4;i++) d[mt][nt][i]=0.f;

    for (int k0=0;k0<K;k0+=32){
        __syncthreads();
#pragma unroll
        for (int it=0;it<4;it++){
            int idx = tid + it*256;
            int r = idx>>3, c4 = (idx&7)*4;
            float4 v = *(const float4*)(A0+(size_t)(row0+r)*K + k0 + c4);
            float4 o;
            o.x=__uint_as_float(tf32_of(v.x)); o.y=__uint_as_float(tf32_of(v.y));
            o.z=__uint_as_float(tf32_of(v.z)); o.w=__uint_as_float(tf32_of(v.w));
            *(float4*)&sA[r][c4] = o;
        }
#pragma unroll
        for (int it=0;it<4;it++){
            int idx = tid + it*256;
            int n = idx>>3, c4 = (idx&7)*4;
            float4 v = *(const float4*)(W+(size_t)n*K + k0 + c4);
            float4 o;
            o.x=__uint_as_float(tf32_of(v.x)); o.y=__uint_as_float(tf32_of(v.y));
            o.z=__uint_as_float(tf32_of(v.z)); o.w=__uint_as_float(tf32_of(v.w));
            *(float4*)&sW[n][c4] = o;
        }
        __syncthreads();
#pragma unroll
        for (int kk=0;kk<32;kk+=8){
            uint32_t af[2][4];
#pragma unroll
            for (int mt=0;mt<2;mt++){
                int mr = wm + mt*16;
                af[mt][0]=__float_as_uint(sA[mr+g  ][kk+q  ]);
                af[mt][1]=__float_as_uint(sA[mr+g+8][kk+q  ]);
                af[mt][2]=__float_as_uint(sA[mr+g  ][kk+q+4]);
                af[mt][3]=__float_as_uint(sA[mr+g+8][kk+q+4]);
            }
            uint32_t bf[8][2];
#pragma unroll
            for (int nt=0;nt<8;nt++){
                int nc = wn + nt*8 + g;
                bf[nt][0]=__float_as_uint(sW[nc][kk+q  ]);
                bf[nt][1]=__float_as_uint(sW[nc][kk+q+4]);
            }
#pragma unroll
            for (int mt=0;mt<2;mt++)
#pragma unroll
                for (int nt=0;nt<8;nt++)
                    mma_tf32(d[mt][nt], af[mt], bf[nt]);
        }
    }
    __syncthreads();

    float* spart = &sA[0][0];
    int wgrp = wid>>2;
#pragma unroll
    for (int mt=0;mt<2;mt++){
#pragma unroll
        for (int half=0;half<2;half++){
            int row = wm + mt*16 + g + half*8;
            float p[8];
#pragma unroll
            for (int j=0;j<8;j++){
                float acc=0.f;
#pragma unroll
                for (int nt=0;nt<8;nt++){
                    int col = wn + nt*8 + 2*q;
                    float b0v = bias[col], b1v = bias[col+1];
                    float h0 = ftanh(d[mt][nt][half*2+0]+b0v);
                    float h1 = ftanh(d[mt][nt][half*2+1]+b1v);
                    acc += h0*sWm[j][col] + h1*sWm[j][col+1];
                }
                p[j]=acc;
            }
#pragma unroll
            for (int j=0;j<8;j++){
                p[j] += __shfl_xor_sync(0xffffffffu, p[j], 1);
                p[j] += __shfl_xor_sync(0xffffffffu, p[j], 2);
            }
            if (q==0){
#pragma unroll
                for (int j=0;j<8;j++)
                    spart[wgrp*1152 + row*9 + j] = p[j];
            }
        }
    }
    __syncthreads();
#pragma unroll
    for (int it=0;it<4;it++){
        int idx = tid + it*256;
        int row = idx>>3, j = idx&7;
        float v = spart[row*9+j] + spart[1152 + row*9 + j] + sbm[j]
                + eps[(size_t)(row0+row)*8 + j];
        aout[(size_t)(row0+row)*8 + j] = v;
    }
}

// ---------------- LSTM + alpha: inputs fully staged in smem (no in-loop LDG) -------
__global__ __launch_bounds__(256)
void lstm_kernel(const float* __restrict__ a, const float* __restrict__ a_init,
                 const float* __restrict__ Wih, const float* __restrict__ Whh,
                 const float* __restrict__ bih, const float* __restrict__ bhh,
                 const float* __restrict__ aW, const float* __restrict__ ab,
                 float* __restrict__ alpha)
{
    __shared__ __align__(16) float4 shv[13];          // h, padded to 52
    __shared__ __align__(16) float sxall[TT_*8];      // x_t for t=0..511 (x_0=a_init)
    __shared__ float spre[200];
    __shared__ __align__(16) float4 saWv[3][13];
    __shared__ float sab_s[3];
    __shared__ float slog[3];
    int tid=threadIdx.x; int b=blockIdx.x;

    float wih[8], whh[52], bsum=0.f, c=0.f;
    if (tid<200){
#pragma unroll
        for (int j=0;j<8;j++) wih[j]=Wih[tid*8+j];
#pragma unroll
        for (int j=0;j<50;j++) whh[j]=Whh[tid*50+j];
        whh[50]=0.f; whh[51]=0.f;
        bsum = bih[tid]+bhh[tid];
    }
    for (int i=tid;i<3*52;i+=256){
        int row=i/52, col=i%52;
        ((float*)saWv)[i] = (col<50)? aW[row*50+col] : 0.f;
    }
    if (tid<3) sab_s[tid]=ab[tid];
    for (int i=tid;i<52;i+=256) ((float*)shv)[i]=0.f;
    // stage ALL inputs: x_0 = a_init; x_t = a[b][t-1] for t>=1 (coalesced, once)
    if (tid<8) sxall[tid]=a_init[tid];
    for (int i=tid;i<(TT_-1)*8;i+=256) sxall[8+i]=a[(size_t)b*TT_*8 + i];
    __syncthreads();

    for (int t=0;t<TT_;t++){
        // ---- P1 ----
        if (tid<200){
            const float4* xv = (const float4*)&sxall[t*8];
            float4 x0=xv[0], x1=xv[1];
            float a0 = bsum + wih[0]*x0.x + wih[4]*x1.x;
            float a1 = wih[1]*x0.y + wih[5]*x1.y;
            float a2 = wih[2]*x0.z + wih[6]*x1.z;
            float a3 = wih[3]*x0.w + wih[7]*x1.w;
#pragma unroll
            for (int q=0;q<13;q++){
                float4 hv=shv[q];
                a0 += whh[4*q+0]*hv.x;
                a1 += whh[4*q+1]*hv.y;
                a2 += whh[4*q+2]*hv.z;
                a3 += whh[4*q+3]*hv.w;
            }
            spre[tid]=(a0+a1)+(a2+a3);
        } else if (tid>=224 && tid<227){
            if (t>0){
                int k=tid-224;
                float a0=0,a1=0,a2=0,a3=0;
#pragma unroll
                for (int q=0;q<13;q++){
                    float4 wv=saWv[k][q], hv=shv[q];
                    a0+=wv.x*hv.x; a1+=wv.y*hv.y; a2+=wv.z*hv.z; a3+=wv.w*hv.w;
                }
                slog[k]=(a0+a1)+(a2+a3)+sab_s[k];
            }
        }
        __syncthreads();
        // ---- P2 ----
        if (tid<50){
            float pi=spre[tid], pf=spre[50+tid], pg=spre[100+tid], po=spre[150+tid];
            float ig=fsig(pi);
            float fg=fsig(pf);
            float gg=ftanh(pg);
            float og=fsig(po);
            c = fg*c + ig*gg;
            ((float*)shv)[tid] = og*ftanh(c);
        } else if (tid>=224 && tid<227 && t>0){
            int k=tid-224;
            float l0=slog[0],l1=slog[1],l2=slog[2];
            float mx=fmaxf(l0,fmaxf(l1,l2));
            float e0=__expf(l0-mx),e1=__expf(l1-mx),e2=__expf(l2-mx);
            float inv=__fdividef(1.f, e0+e1+e2);
            float mine=(k==0)?e0:((k==1)?e1:e2);
            alpha[((size_t)b*TT_+t-1)*3+k]=mine*inv;
        }
        __syncthreads();
    }
    // final alpha (t = T-1) from h_{T-1}
    if (tid>=224 && tid<227){
        int k=tid-224;
        float lg[3];
#pragma unroll
        for (int kk=0;kk<3;kk++){
            float a0=0,a1=0,a2=0,a3=0;
#pragma unroll
            for (int q=0;q<13;q++){
                float4 wv=saWv[kk][q], hv=shv[q];
                a0+=wv.x*hv.x; a1+=wv.y*hv.y; a2+=wv.z*hv.z; a3+=wv.w*hv.w;
            }
            lg[kk]=(a0+a1)+(a2+a3)+sab_s[kk];
        }
        float mx=fmaxf(lg[0],fmaxf(lg[1],lg[2]));
        float e0=__expf(lg[0]-mx),e1=__expf(lg[1]-mx),e2=__expf(lg[2]-mx);
        float inv=__fdividef(1.f, e0+e1+e2);
        float mine=(k==0)?e0:((k==1)?e1:e2);
        alpha[((size_t)b*TT_+TT_-1)*3+k]=mine*inv;
    }
}

// ======================== Kalman forward: register-table uniform phases ============
#define KO_AM   0
#define KO_BM   16
#define KO_CM   52
#define KO_SIG  84
#define KO_SIGP 100
#define KO_PADJ 116
#define KO_CTC  132
#define KO_N    148
#define KO_NADJ 164
#define KO_T2   180
#define KO_JT   196
#define KO_W    212
#define KO_MU   244
#define KO_MUP  248
#define KO_RES  252
#define KO_AT   260
#define KO_UT   268
#define KO_SC   280
#define KO_ONE  284
#define KO_ZERO 285
#define KO_IRC  286
#define KO_QNS  287
#define KWSZ    288

__device__ __forceinline__ uint32_t kenc(int ia,int ib,int ic,int neg){
    return (uint32_t)ia | ((uint32_t)ib<<9) | ((uint32_t)ic<<18) | ((uint32_t)neg<<31);
}

// Uniform signed triple-product accumulation; table entries live in REGISTERS.
template<int T>
__device__ __forceinline__ float phase_dot_r(const float* __restrict__ s,
                                             const uint32_t (&tab)[T]){
    float a0=0.f, a1=0.f;
#pragma unroll
    for (int m=0;m<T;m++){
        uint32_t e = tab[m];
        float v = s[e & 511u] * s[(e>>9) & 511u] * s[(e>>18) & 511u];
        float sg = __int_as_float(0x3f800000u | (e & 0x80000000u));
        if (m & 1) a1 = fmaf(v, sg, a1); else a0 = fmaf(v, sg, a0);
    }
    return a0 + a1;
}

__global__ __launch_bounds__(64)
void kf_forward(const float* __restrict__ alpha, const float* __restrict__ a,
                const float* __restrict__ a_init, const float* __restrict__ u_ext,
                const float* __restrict__ Ag, const float* __restrict__ Bg,
                const float* __restrict__ Cg,
                float* __restrict__ mu_p_g, float* __restrict__ mu_f_g,
                float* __restrict__ Jg)
{
    __shared__ float sCat[3*84];
    __shared__ float wsm[2][KWSZ];
    __shared__ uint32_t tb2[16*32], tb3[8*32], tb4[8*32], tb5[8*32], tb6[6*32];
    __shared__ uint32_t aux2[32], aux3[32], aux4[32], aux5[32], aux6[32];

    const float ir = 1.f/0.03f;
    int w = threadIdx.x>>5, ln = threadIdx.x&31;
    int b = blockIdx.x*2 + w;

    for (int i=threadIdx.x;i<48;i+=64){ int k=i/16, f=i%16;  sCat[k*84+f]      = Ag[i]; }
    for (int i=threadIdx.x;i<108;i+=64){int k=i/36, f=i%36;  sCat[k*84+16+f]   = Bg[i]; }
    for (int i=threadIdx.x;i<96;i+=64){ int k=i/32, f=i%32;  sCat[k*84+52+f]   = Cg[i]; }
    if (threadIdx.x<2){
        float* s0 = wsm[threadIdx.x];
        s0[KO_ONE]=1.f; s0[KO_ZERO]=0.f; s0[KO_IRC]=ir; s0[KO_QNS]=0.08f;
        for (int i=0;i<16;i++) s0[KO_SIG+i]=0.f;
        for (int i=0;i<4;i++)  s0[KO_MU+i]=0.f;
    }

    if (threadIdx.x==0){
        const uint32_t ZT = kenc(KO_ZERO,KO_ZERO,KO_ZERO,0);
        const int PI_[10]={0,0,0,0,1,1,1,2,2,3};
        const int PJ_[10]={0,1,2,3,1,2,3,2,3,3};
        const int P3p[6][3]={{0,1,2},{0,2,1},{1,0,2},{1,2,0},{2,0,1},{2,1,0}};
        const int SG3[6]={0,1,1,0,0,1};
        for (int l=0;l<32;l++){
            uint32_t init=KO_ZERO, out=KO_ZERO, mir=KO_ZERO;
            for (int m=0;m<16;m++) tb2[m*32+l]=ZT;
            if (l<16){
                int i=l>>2, j=l&3;
                for (int m=0;m<16;m++){
                    int k=m>>2, q=m&3;
                    tb2[m*32+l]=kenc(KO_AM+i*4+k, KO_SIG+k*4+q, KO_AM+j*4+q, 0);
                }
                init=(i==j)?KO_QNS:KO_ZERO; out=KO_SIGP+l; mir=out;
            } else if (l<20){
                int r=l-16;
                for (int m=0;m<4;m++)  tb2[m*32+l]=kenc(KO_AM+r*4+m, KO_MU+m, KO_ONE, 0);
                for (int m=4;m<13;m++) tb2[m*32+l]=kenc(KO_BM+r*9+(m-4), KO_UT+(m-4), KO_ONE, 0);
                out=KO_MUP+r; mir=out;
            } else if (l<30){
                int p=l-20, pi=PI_[p], pj=PJ_[p];
                for (int m=0;m<8;m++) tb2[m*32+l]=kenc(KO_CM+m*4+pi, KO_CM+m*4+pj, KO_IRC, 0);
                out=KO_CTC+pi*4+pj; mir=KO_CTC+pj*4+pi;
            }
            aux2[l]= init | (out<<9) | (mir<<18);
        }
        for (int l=0;l<32;l++){
            for (int m=0;m<8;m++) tb3[m*32+l]=ZT;
            uint32_t out=KO_ZERO;
            if (l<16){
                int r=l>>2, c=l&3;
                int rr[3], cc[3]; int p=0;
                for (int k=0;k<4;k++) if (k!=c) rr[p++]=k;
                p=0;
                for (int k=0;k<4;k++) if (k!=r) cc[p++]=k;
                int base=(r+c)&1;
                for (int m=0;m<6;m++){
                    tb3[m*32+l]=kenc(KO_SIGP+rr[0]*4+cc[P3p[m][0]],
                                     KO_SIGP+rr[1]*4+cc[P3p[m][1]],
                                     KO_SIGP+rr[2]*4+cc[P3p[m][2]], SG3[m]^base);
                }
                out=KO_PADJ+l;
            } else {
                int l2=l-16, i=l2>>2, j=l2&3;
                for (int m=0;m<4;m++) tb3[m*32+l]=kenc(KO_SIG+i*4+m, KO_AM+j*4+m, KO_ONE, 0);
                out=KO_T2+l2;
            }
            aux3[l]=out;
        }
        for (int l=0;l<32;l++){
            for (int m=0;m<8;m++) tb4[m*32+l]=ZT;
            uint32_t out=KO_ZERO;
            if (l<16){
                int i=l>>2, j=l&3;
                for (int m=0;m<4;m++) tb4[m*32+l]=kenc(KO_T2+i*4+m, KO_PADJ+m*4+j, KO_ONE, 0);
                out=KO_JT+l;
            } else if (l<24){
                int cc=l-16;
                tb4[0*32+l]=kenc(KO_AT+cc, KO_ONE, KO_ONE, 0);
                for (int m=1;m<5;m++) tb4[m*32+l]=kenc(KO_CM+cc*4+(m-1), KO_MUP+(m-1), KO_ONE, 1);
                out=KO_RES+cc;
            } else if (l==24){
                for (int m=0;m<4;m++) tb4[m*32+l]=kenc(KO_SIGP+m, KO_PADJ+m*4, KO_ONE, 0);
                out=KO_SC+0;
            }
            aux4[l]=out;
        }
        for (int l=0;l<32;l++){
            for (int m=0;m<8;m++) tb5[m*32+l]=ZT;
            uint32_t out=KO_ZERO;
            if (l<16){
                tb5[0*32+l]=kenc(KO_PADJ+l, KO_ONE, KO_ONE, 0);
                tb5[1*32+l]=kenc(KO_SC+0, KO_CTC+l, KO_ONE, 0);
                out=KO_N+l;
            } else if (l<20){
                int i=l-16;
                for (int m=0;m<8;m++) tb5[m*32+l]=kenc(KO_CM+m*4+i, KO_RES+m, KO_ONE, 0);
                out=KO_W+i;
            }
            aux5[l]=out;
        }
        for (int l=0;l<32;l++){
            for (int m=0;m<6;m++) tb6[m*32+l]=ZT;
            uint32_t out=KO_ZERO;
            if (l<16){
                int r=l>>2, c=l&3;
                int rr[3], cc[3]; int p=0;
                for (int k=0;k<4;k++) if (k!=c) rr[p++]=k;
                p=0;
                for (int k=0;k<4;k++) if (k!=r) cc[p++]=k;
                int base=(r+c)&1;
                for (int m=0;m<6;m++){
                    tb6[m*32+l]=kenc(KO_N+rr[0]*4+cc[P3p[m][0]],
                                     KO_N+rr[1]*4+cc[P3p[m][1]],
                                     KO_N+rr[2]*4+cc[P3p[m][2]], SG3[m]^base);
                }
                out=KO_NADJ+l;
            }
            aux6[l]=out;
        }
    }
    __syncthreads();
    float* s = wsm[w];

    // hoist tables into registers (loop-invariant; removes per-step indirection LDS)
    uint32_t rt2[16], rt3[8], rt4[8], rt5[8], rt6[6];
#pragma unroll
    for (int m=0;m<16;m++) rt2[m]=tb2[m*32+ln];
#pragma unroll
    for (int m=0;m<8;m++)  rt3[m]=tb3[m*32+ln];
#pragma unroll
    for (int m=0;m<8;m++)  rt4[m]=tb4[m*32+ln];
#pragma unroll
    for (int m=0;m<8;m++)  rt5[m]=tb5[m*32+ln];
#pragma unroll
    for (int m=0;m<6;m++)  rt6[m]=tb6[m*32+ln];
    const uint32_t a2 = aux2[ln], a3 = aux3[ln], a4 = aux4[ln], a5 = aux5[ln], a6 = aux6[ln];

    float r_al=0.f, r_a=0.f, r_u=0.f, r_ap=0.f;
    if (ln<3)            r_al = alpha[(size_t)b*TT_*3 + ln];
    if (ln>=4 && ln<12){ r_a  = a[(size_t)b*TT_*8 + (ln-4)]; r_ap = a_init[ln-4]; }
    if (ln==12)          r_u  = u_ext[(size_t)b*TT_];

    for (int t=0;t<TT_;t++){
        size_t bt = (size_t)b*TT_ + t;
        float al0=__shfl_sync(0xffffffffu, r_al, 0);
        float al1=__shfl_sync(0xffffffffu, r_al, 1);
        float al2=__shfl_sync(0xffffffffu, r_al, 2);
#pragma unroll
        for (int it=0;it<3;it++){
            int f = ln + it*32;
            if (f<84)
                s[f] = al0*sCat[f] + al1*sCat[84+f] + al2*sCat[168+f];
        }
        if (ln>=4 && ln<12){ s[KO_AT+ln-4]=r_a; s[KO_UT+ln-4]=r_ap; r_ap=r_a; }
        if (ln==12) s[KO_UT+8]=r_u;
        if (t+1<TT_){
            if (ln<3)            r_al = alpha[(bt+1)*3+ln];
            if (ln>=4 && ln<12)  r_a  = a[(bt+1)*8 + (ln-4)];
            if (ln==12)          r_u  = u_ext[bt+1];
        }
        __syncwarp();
        {
            float acc = phase_dot_r<16>(s, rt2) + s[a2 & 511u];
            s[(a2>>9) & 511u] = acc;
            s[(a2>>18) & 511u] = acc;
            if (t==0){
                if (ln<16) s[KO_SIGP+ln] = ((ln>>2)==(ln&3))? 20.f : 0.f;
                else if (ln<20) s[KO_MUP+ln-16]=0.f;
            }
        }
        __syncwarp();
        s[a3] = phase_dot_r<8>(s, rt3);
        __syncwarp();
        s[a4] = phase_dot_r<8>(s, rt4);
        __syncwarp();
        s[a5] = phase_dot_r<8>(s, rt5);
        __syncwarp();
        s[a6] = phase_dot_r<6>(s, rt6);
        if (ln>=16 && t>0){
            int l2=ln-16;
            Jg[(bt-1)*16 + l2] = __fdividef(s[KO_JT+l2], s[KO_SC+0]);
        }
        __syncwarp();
        if (ln<16){
            float dn = s[KO_N+0]*s[KO_NADJ+0] + s[KO_N+1]*s[KO_NADJ+4]
                     + s[KO_N+2]*s[KO_NADJ+8] + s[KO_N+3]*s[KO_NADJ+12];
            float sc = __fdividef(s[KO_SC+0], dn);
            s[KO_SIG+ln] = s[KO_NADJ+ln]*sc;
        } else if (ln<20){
            int r=ln-16;
            float dn = s[KO_N+0]*s[KO_NADJ+0] + s[KO_N+1]*s[KO_NADJ+4]
                     + s[KO_N+2]*s[KO_NADJ+8] + s[KO_N+3]*s[KO_NADJ+12];
            float sc = __fdividef(s[KO_SC+0], dn);
            float acc=0.f;
#pragma unroll
            for (int k=0;k<4;k++) acc += s[KO_NADJ+r*4+k]*s[KO_W+k];
            float v = s[KO_MUP+r] + acc*sc*ir;
            s[KO_MU+r]=v;
            mu_f_g[bt*4+r]=v;
        } else if (ln<24){
            mu_p_g[bt*4+ln-20]=s[KO_MUP+ln-20];
        }
        __syncwarp();
    }
}

// ---------------- backward mu_smooth + ahat fused (4 lanes per batch) ---------------
__global__ __launch_bounds__(32)
void smooth_ahat_kernel(const float* __restrict__ mu_f, const float* __restrict__ mu_p,
                        const float* __restrict__ Jg, const float* __restrict__ alpha,
                        const float* __restrict__ Cg, float* __restrict__ ahat)
{
    __shared__ float sCg[96];
    int tid = threadIdx.x;
    for (int i=tid;i<96;i+=32) sCg[i]=Cg[i];
    __syncthreads();
    int g = blockIdx.x*8 + (tid>>2);
    int i = tid & 3;
    size_t base = (size_t)g*TT_;
    unsigned gb = tid & ~3u;

    float v = mu_f[(base+TT_-1)*4 + i];
    float alv = (i<3)? alpha[(base+TT_-1)*3 + i] : 0.f;

    auto emit = [&](size_t btIdx, float vloc, float alLoc){
        float m0=__shfl_sync(0xffffffffu, vloc, gb+0);
        float m1=__shfl_sync(0xffffffffu, vloc, gb+1);
        float m2=__shfl_sync(0xffffffffu, vloc, gb+2);
        float m3=__shfl_sync(0xffffffffu, vloc, gb+3);
        float b0=__shfl_sync(0xffffffffu, alLoc, gb+0);
        float b1=__shfl_sync(0xffffffffu, alLoc, gb+1);
        float b2=__shfl_sync(0xffffffffu, alLoc, gb+2);
        float2 o;
#pragma unroll
        for (int e=0;e<2;e++){
            int r = i*2+e;
            float acc=0.f;
#pragma unroll
            for (int k=0;k<3;k++){
                const float* c = &sCg[k*32 + r*4];
                float dotv = c[0]*m0 + c[1]*m1 + c[2]*m2 + c[3]*m3;
                float bk = (k==0)?b0:((k==1)?b1:b2);
                acc += bk*dotv;
            }
            if (e==0) o.x=acc; else o.y=acc;
        }
        *(float2*)&ahat[btIdx*8 + i*2] = o;
    };

    emit(base+TT_-1, v, alv);

    float4 Jr = *(const float4*)&Jg[(base+TT_-2)*16 + i*4];
    float mf = mu_f[(base+TT_-2)*4 + i];
    float mp = mu_p[(base+TT_-1)*4 + i];
    alv = (i<3)? alpha[(base+TT_-2)*3 + i] : 0.f;

    for (int t=TT_-2; t>=0; t--){
        float4 Jn; float mfn=0.f, mpn=0.f, aln=0.f;
        if (t>0){
            Jn  = *(const float4*)&Jg[(base+t-1)*16 + i*4];
            mfn = mu_f[(base+t-1)*4 + i];
            mpn = mu_p[(base+t)*4 + i];
            aln = (i<3)? alpha[(base+t-1)*3 + i] : 0.f;
        } else { Jn = Jr; }
        float mi = v - mp;
        float m0=__shfl_sync(0xffffffffu, mi, gb+0);
        float m1=__shfl_sync(0xffffffffu, mi, gb+1);
        float m2=__shfl_sync(0xffffffffu, mi, gb+2);
        float m3=__shfl_sync(0xffffffffu, mi, gb+3);
        v = mf + Jr.x*m0 + Jr.y*m1 + Jr.z*m2 + Jr.w*m3;
        emit(base+t, v, alv);
        Jr=Jn; mf=mfn; mp=mpn; alv=aln;
    }
}

// ---------------- decoder layer 1: d1 = tanh(ahat @ W^T + b) (K=8) ------------------
__global__ __launch_bounds__(256)
void dec1_kernel(const float* __restrict__ ahat, const float* __restrict__ W,
                 const float* __restrict__ bvec, float* __restrict__ out)
{
    __shared__ float sa[16][8];
    int tid = threadIdx.x;
    int r0 = blockIdx.x*16;
    if (tid<128) sa[tid>>3][tid&7] = ahat[(size_t)r0*8 + tid];
    int n = tid & 127;
    float w[8];
#pragma unroll
    for (int j=0;j<8;j++) w[j]=W[n*8+j];
    float bb=bvec[n];
    __syncthreads();
    int half = tid>>7;
#pragma unroll
    for (int q=0;q<8;q++){
        int rl = half*8+q;
        float s=bb;
#pragma unroll
        for (int j=0;j<8;j++) s += sa[rl][j]*w[j];
        out[(size_t)(r0+rl)*128 + n] = ftanh(s);
    }
}

// ---------------- launcher ----------------------------------------------------------
extern "C" void kernel_launch(void* const* d_in, const int* in_sizes, int n_in,
                              void* d_out, int out_size)
{
    const float* x       = (const float*)d_in[0];
    const float* m       = (const float*)d_in[1];
    const float* u_ext   = (const float*)d_in[2];
    const float* eps     = (const float*)d_in[3];
    const float* enc_W1  = (const float*)d_in[4];
    const float* enc_b1  = (const float*)d_in[5];
    const float* enc_W2  = (const float*)d_in[6];
    const float* enc_b2  = (const float*)d_in[7];
    const float* W_mean  = (const float*)d_in[8];
    const float* b_mean  = (const float*)d_in[9];
    const float* Amat    = (const float*)d_in[10];
    const float* Bmat    = (const float*)d_in[11];
    const float* Cmat    = (const float*)d_in[12];
    const float* a_init  = (const float*)d_in[13];
    const float* lstm_Wih= (const float*)d_in[14];
    const float* lstm_Whh= (const float*)d_in[15];
    const float* lstm_bih= (const float*)d_in[16];
    const float* lstm_bhh= (const float*)d_in[17];
    const float* alpha_W = (const float*)d_in[18];
    const float* alpha_b = (const float*)d_in[19];
    const float* dec_W1  = (const float*)d_in[20];
    const float* dec_b1  = (const float*)d_in[21];
    const float* dec_W2  = (const float*)d_in[22];
    const float* dec_b2  = (const float*)d_in[23];
    const float* gen_W   = (const float*)d_in[24];
    const float* gen_b   = (const float*)d_in[25];

    float *p_buf1,*p_buf2,*p_a,*p_alpha,*p_mup,*p_muf,*p_J,*p_ahat;
    cudaGetSymbolAddress((void**)&p_buf1,  g_buf1);
    cudaGetSymbolAddress((void**)&p_buf2,  g_buf2);
    cudaGetSymbolAddress((void**)&p_a,     g_a);
    cudaGetSymbolAddress((void**)&p_alpha, g_alpha);
    cudaGetSymbolAddress((void**)&p_mup,   g_mup);
    cudaGetSymbolAddress((void**)&p_muf,   g_muf);
    cudaGetSymbolAddress((void**)&p_J,     g_J);
    cudaGetSymbolAddress((void**)&p_ahat,  g_ahat);

    // encoder: GEMM1, then GEMM2 with enc3 fused into epilogue (h2 stays on-chip)
    tgemm128<1,true ><<<NROWS/128,256>>>(x, m, enc_W1, enc_b1, p_buf1, 256);
    tgemm128_enc<<<NROWS/128,256>>>(p_buf1, enc_W2, enc_b2, W_mean, b_mean, eps, p_a);
    // LSTM -> alpha (inputs fully staged in smem)
    lstm_kernel<<<BSZ,256>>>(p_a, a_init, lstm_Wih, lstm_Whh, lstm_bih, lstm_bhh,
                             alpha_W, alpha_b, p_alpha);
    // Kalman forward (+ fused smoother gains J), register-table phases
    kf_forward<<<BSZ/2,64>>>(p_alpha, p_a, a_init, u_ext, Amat, Bmat, Cmat,
                             p_mup, p_muf, p_J);
    // backward mu recursion + ahat fused
    smooth_ahat_kernel<<<32,32>>>(p_muf, p_mup, p_J, p_alpha, Cmat, p_ahat);
    // decoder
    dec1_kernel<<<NROWS/16,256>>>(p_ahat, dec_W1, dec_b1, p_buf1);
    tgemm128<1,false><<<NROWS/128,256>>>(p_buf1, nullptr, dec_W2, dec_b2, p_buf2, 128);
    tgemm128<2,false><<<NROWS/128,256>>>(p_buf2, nullptr, gen_W, gen_b, (float*)d_out, 128);
    (void)in_sizes; (void)n_in; (void)out_size;
}